// round 1
// baseline (speedup 1.0000x reference)
#include <cuda_runtime.h>
#include <cuda_bf16.h>
#include <math.h>

#define BATCH 4
#define SEQ   2048
#define CDIM  2048
#define NH    16
#define NKV   4
#define HD    128
#define KVC   1024   // 2*NKV*HD

// Scratch (device globals: allocation-free per harness rules)
__device__ float g_q [BATCH * SEQ * CDIM];   // q projection  [B*T, C]
__device__ float g_kv[BATCH * SEQ * KVC];    // kv projection [B*T, 1024]
__device__ float g_y [BATCH * SEQ * CDIM];   // attention out [B*T, C]

// ---------------------------------------------------------------------------
// SGEMM: C[M,N] = A[M,K] @ B[K,N] (+ bias), row-major, all dims %128==0, K%8==0
// 128x128 block tile, BK=8, 8x8 per thread, 256 threads.
// B-columns owned strided (tx + 16*j) -> conflict-free scalar Bs reads.
// ---------------------------------------------------------------------------
__global__ __launch_bounds__(256) void sgemm_kernel(
    const float* __restrict__ A, const float* __restrict__ B,
    const float* __restrict__ bias, float* __restrict__ C,
    int M, int N, int K)
{
    __shared__ float As[8][128];   // transposed A tile
    __shared__ float Bs[8][128];

    const int tid = threadIdx.x;
    const int bx = blockIdx.x, by = blockIdx.y;

    const float* Ab = A + (size_t)by * 128 * K;
    const float* Bb = B + (size_t)bx * 128;

    const int arow = tid >> 1, acol = (tid & 1) * 4;   // A tile load map
    const int brow = tid >> 5, bcol = (tid & 31) * 4;  // B tile load map
    const int ty = tid >> 4, tx = tid & 15;

    float acc[8][8];
#pragma unroll
    for (int i = 0; i < 8; i++)
#pragma unroll
        for (int j = 0; j < 8; j++) acc[i][j] = 0.f;

    for (int k0 = 0; k0 < K; k0 += 8) {
        float4 a4 = *(const float4*)(Ab + (size_t)arow * K + k0 + acol);
        As[acol + 0][arow] = a4.x;
        As[acol + 1][arow] = a4.y;
        As[acol + 2][arow] = a4.z;
        As[acol + 3][arow] = a4.w;
        float4 b4 = *(const float4*)(Bb + (size_t)(k0 + brow) * N + bcol);
        *(float4*)&Bs[brow][bcol] = b4;
        __syncthreads();

#pragma unroll
        for (int kk = 0; kk < 8; kk++) {
            float af[8], bf[8];
            *(float4*)(af)     = *(float4*)&As[kk][ty * 8];
            *(float4*)(af + 4) = *(float4*)&As[kk][ty * 8 + 4];
#pragma unroll
            for (int j = 0; j < 8; j++) bf[j] = Bs[kk][tx + 16 * j];
#pragma unroll
            for (int i = 0; i < 8; i++)
#pragma unroll
                for (int j = 0; j < 8; j++)
                    acc[i][j] += af[i] * bf[j];
        }
        __syncthreads();
    }

#pragma unroll
    for (int i = 0; i < 8; i++) {
        size_t row = (size_t)by * 128 + ty * 8 + i;
#pragma unroll
        for (int j = 0; j < 8; j++) {
            int col = bx * 128 + tx + 16 * j;
            float v = acc[i][j];
            if (bias) v += bias[col];
            C[row * N + col] = v;
        }
    }
}

// ---------------------------------------------------------------------------
// Flash attention (fp32, causal, GQA): grid (T/64, H, B), 256 threads.
// 64 query rows x 64 key cols per tile, D=128. Online softmax.
// Smem: Qs/Ks/Vs [64][132] + Ss [64][68] + m/l/alpha -> ~117 KB dynamic.
// ---------------------------------------------------------------------------
__global__ __launch_bounds__(256) void flash_kernel()
{
    extern __shared__ float sm[];
    float* Qs   = sm;                   // [64][132]
    float* Ks   = sm + 64 * 132;        // [64][132]
    float* Vs   = sm + 2 * 64 * 132;    // [64][132]
    float* Ss   = sm + 3 * 64 * 132;    // [64][68]
    float* Mrow = Ss + 64 * 68;         // [64]
    float* Lrow = Mrow + 64;            // [64]
    float* Arow = Lrow + 64;            // [64]

    const int tid  = threadIdx.x;
    const int b    = blockIdx.z;
    const int h    = blockIdx.y;
    const int hkv  = h >> 2;            // G = 4
    const int row0 = blockIdx.x * 64;
    const float scale = 0.08838834764831845f;   // 1/sqrt(128)

    // Load Q tile [64 rows][128 d]
    for (int idx = tid; idx < 64 * 32; idx += 256) {
        int r = idx >> 5, d4 = idx & 31;
        float4 q4 = *(const float4*)&g_q[((size_t)(b * SEQ + row0 + r)) * CDIM + h * HD + d4 * 4];
        *(float4*)&Qs[r * 132 + d4 * 4] = q4;
    }
    if (tid < 64) { Mrow[tid] = -1e30f; Lrow[tid] = 0.f; }

    const int ty = tid >> 4, tx = tid & 15;
    const int r0 = ty * 4;

    float o[4][8];
#pragma unroll
    for (int i = 0; i < 4; i++)
#pragma unroll
        for (int j = 0; j < 8; j++) o[i][j] = 0.f;

    const int ntiles = blockIdx.x + 1;     // causal: keys 0 .. row0+63
    for (int jt = 0; jt < ntiles; ++jt) {
        const int col0 = jt * 64;
        __syncthreads();   // prev iter done with Ks/Vs/Ss; Q/m/l visible on iter 0

        // Load K, V tiles
        for (int idx = tid; idx < 64 * 32; idx += 256) {
            int r = idx >> 5, d4 = idx & 31;
            size_t base = ((size_t)(b * SEQ + col0 + r)) * KVC + hkv * HD + d4 * 4;
            *(float4*)&Ks[r * 132 + d4 * 4] = *(const float4*)&g_kv[base];
            *(float4*)&Vs[r * 132 + d4 * 4] = *(const float4*)&g_kv[base + 512];
        }
        __syncthreads();

        // S = Q K^T  (thread covers rows r0..r0+3, cols tx+16*j)
        float acc[4][4];
#pragma unroll
        for (int i = 0; i < 4; i++)
#pragma unroll
            for (int j = 0; j < 4; j++) acc[i][j] = 0.f;

#pragma unroll 4
        for (int d4 = 0; d4 < 32; ++d4) {
            float4 qf[4], kf[4];
#pragma unroll
            for (int i = 0; i < 4; i++) qf[i] = *(float4*)&Qs[(r0 + i) * 132 + d4 * 4];
#pragma unroll
            for (int j = 0; j < 4; j++) kf[j] = *(float4*)&Ks[(tx + 16 * j) * 132 + d4 * 4];
#pragma unroll
            for (int i = 0; i < 4; i++)
#pragma unroll
                for (int j = 0; j < 4; j++) {
                    acc[i][j] += qf[i].x * kf[j].x;
                    acc[i][j] += qf[i].y * kf[j].y;
                    acc[i][j] += qf[i].z * kf[j].z;
                    acc[i][j] += qf[i].w * kf[j].w;
                }
        }

        // scale + causal mask + store S
#pragma unroll
        for (int i = 0; i < 4; i++) {
            int rq = row0 + r0 + i;
#pragma unroll
            for (int j = 0; j < 4; j++) {
                int c = col0 + tx + 16 * j;
                float s = (c <= rq) ? acc[i][j] * scale : -1e30f;
                Ss[(r0 + i) * 68 + tx + 16 * j] = s;
            }
        }
        __syncthreads();

        // Online softmax: 4 lanes per row, 16 cols each
        {
            const int rr = tid >> 2;
            const int c0 = (tid & 3) * 16;
            float mloc = -1e30f;
#pragma unroll
            for (int c = 0; c < 16; c++) mloc = fmaxf(mloc, Ss[rr * 68 + c0 + c]);
            mloc = fmaxf(mloc, __shfl_xor_sync(0xffffffffu, mloc, 1));
            mloc = fmaxf(mloc, __shfl_xor_sync(0xffffffffu, mloc, 2));
            float mold = Mrow[rr];
            float mnew = fmaxf(mold, mloc);
            float lloc = 0.f;
#pragma unroll
            for (int c = 0; c < 16; c++) {
                float p = __expf(Ss[rr * 68 + c0 + c] - mnew);
                Ss[rr * 68 + c0 + c] = p;
                lloc += p;
            }
            lloc += __shfl_xor_sync(0xffffffffu, lloc, 1);
            lloc += __shfl_xor_sync(0xffffffffu, lloc, 2);
            if ((tid & 3) == 0) {
                float alpha = __expf(mold - mnew);   // mold=-1e30 -> 0
                Mrow[rr] = mnew;
                Lrow[rr] = Lrow[rr] * alpha + lloc;
                Arow[rr] = alpha;
            }
        }
        __syncthreads();

        // O = alpha*O + P @ V   (thread: rows r0..r0+3, cols tx+16*jj)
        float al[4];
#pragma unroll
        for (int i = 0; i < 4; i++) al[i] = Arow[r0 + i];
#pragma unroll
        for (int i = 0; i < 4; i++)
#pragma unroll
            for (int jj = 0; jj < 8; jj++) o[i][jj] *= al[i];

#pragma unroll 4
        for (int c = 0; c < 64; ++c) {
            float p0 = Ss[(r0 + 0) * 68 + c];
            float p1 = Ss[(r0 + 1) * 68 + c];
            float p2 = Ss[(r0 + 2) * 68 + c];
            float p3 = Ss[(r0 + 3) * 68 + c];
#pragma unroll
            for (int jj = 0; jj < 8; jj++) {
                float v = Vs[c * 132 + tx + 16 * jj];
                o[0][jj] += p0 * v;
                o[1][jj] += p1 * v;
                o[2][jj] += p2 * v;
                o[3][jj] += p3 * v;
            }
        }
    }

    // Normalize and store
#pragma unroll
    for (int i = 0; i < 4; i++) {
        float linv = 1.f / Lrow[r0 + i];
        size_t base = ((size_t)(b * SEQ + row0 + r0 + i)) * CDIM + h * HD;
#pragma unroll
        for (int jj = 0; jj < 8; jj++)
            g_y[base + tx + 16 * jj] = o[i][jj] * linv;
    }
}

// ---------------------------------------------------------------------------
extern "C" void kernel_launch(void* const* d_in, const int* in_sizes, int n_in,
                              void* d_out, int out_size)
{
    const float* x   = (const float*)d_in[0];
    const float* Wq  = (const float*)d_in[1];
    const float* Wkv = (const float*)d_in[2];
    const float* Wc  = (const float*)d_in[3];
    const float* bc  = (const float*)d_in[4];
    float* out = (float*)d_out;

    float *qb, *kvb, *yb;
    cudaGetSymbolAddress((void**)&qb,  g_q);
    cudaGetSymbolAddress((void**)&kvb, g_kv);
    cudaGetSymbolAddress((void**)&yb,  g_y);

    const int M = BATCH * SEQ;   // 8192
    dim3 blk(256);

    // q = x @ Wq   [8192, 2048]
    sgemm_kernel<<<dim3(CDIM / 128, M / 128), blk>>>(x, Wq, nullptr, qb, M, CDIM, CDIM);
    // kv = x @ Wkv [8192, 1024]
    sgemm_kernel<<<dim3(KVC / 128, M / 128), blk>>>(x, Wkv, nullptr, kvb, M, KVC, CDIM);

    // flash attention
    size_t smem = (size_t)(3 * 64 * 132 + 64 * 68 + 3 * 64) * sizeof(float);
    cudaFuncSetAttribute(flash_kernel, cudaFuncAttributeMaxDynamicSharedMemorySize, (int)smem);
    flash_kernel<<<dim3(SEQ / 64, NH, BATCH), blk, smem>>>();

    // out = y @ Wc + bc
    sgemm_kernel<<<dim3(CDIM / 128, M / 128), blk>>>(yb, Wc, bc, out, M, CDIM, CDIM);
}

// round 6
// speedup vs baseline: 2.2822x; 2.2822x over previous
#include <cuda_runtime.h>
#include <cuda_bf16.h>
#include <math.h>

#define BATCH 4
#define SEQ   2048
#define CDIM  2048
#define NH    16
#define NKV   4
#define HD    128
#define KVC   1024   // 2*NKV*HD

// Scratch (device globals: allocation-free per harness rules)
__device__ float g_q [BATCH * SEQ * CDIM];   // q projection  [B*T, C]
__device__ float g_kv[BATCH * SEQ * KVC];    // kv projection [B*T, 1024]
__device__ float g_y [BATCH * SEQ * CDIM];   // attention out [B*T, C]

// ---------------------------------------------------------------------------
// TF32 tensor-core GEMM: C[M,N] = A[M,K] @ B[K,N] (+ bias), row-major.
// 128x128 block tile, BK=16, 256 threads (8 warps as 2x4 -> 64x32 per warp).
// mma.sync.m16n8k8.tf32, fp32 accumulate. Double-buffered smem.
// As: k-major, stride 136, XOR swizzle col = r ^ (8*((k>>2)&3))
//     -> conflict-free transposing stores AND fragment reads.
// Bs: k-major row layout, stride 136 -> conflict-free (k->tg, col->gid).
// ---------------------------------------------------------------------------
#define GS_AS 136
#define GS_BS 136

__device__ __forceinline__ unsigned f2tf32(float f) {
    unsigned u;
    asm("cvt.rna.tf32.f32 %0, %1;" : "=r"(u) : "f"(f));
    return u;
}

__device__ __forceinline__ void mma_tf32(float c[4],
    unsigned a0, unsigned a1, unsigned a2, unsigned a3,
    unsigned b0, unsigned b1)
{
    asm volatile(
        "mma.sync.aligned.m16n8k8.row.col.f32.tf32.tf32.f32 "
        "{%0,%1,%2,%3}, {%4,%5,%6,%7}, {%8,%9}, {%0,%1,%2,%3};"
        : "+f"(c[0]), "+f"(c[1]), "+f"(c[2]), "+f"(c[3])
        : "r"(a0), "r"(a1), "r"(a2), "r"(a3), "r"(b0), "r"(b1));
}

__global__ __launch_bounds__(256, 1) void gemm_tf32_kernel(
    const float* __restrict__ A, const float* __restrict__ B,
    const float* __restrict__ bias, float* __restrict__ C,
    int M, int N, int K)
{
    __shared__ unsigned As[2][16][GS_AS];
    __shared__ unsigned Bs[2][16][GS_BS];

    const int tid  = threadIdx.x;
    const int lane = tid & 31;
    const int warp = tid >> 5;
    const int tg   = lane & 3;
    const int gid  = lane >> 2;
    const int warpM = (warp & 1) * 64;       // 2 warps in M
    const int warpN = (warp >> 1) * 32;      // 4 warps in N

    const int blockRow = blockIdx.y * 128;
    const int blockCol = blockIdx.x * 128;

    // gmem load mapping
    const int aRow  = tid >> 2;            // 0..63 (and +64)
    const int aCol0 = (tid & 3) * 4;       // k offset within tile
    const int bRow  = tid >> 5;            // 0..7 (and +8)
    const int bCol0 = (tid & 31) * 4;      // col offset

    const float* Ag = A + (size_t)(blockRow) * K;
    const float* Bg = B + blockCol;

    float c[4][4][4];
#pragma unroll
    for (int mt = 0; mt < 4; mt++)
#pragma unroll
        for (int nt = 0; nt < 4; nt++)
#pragma unroll
            for (int i = 0; i < 4; i++) c[mt][nt][i] = 0.f;

    const int nT = K / 16;

    // ---- prologue: load tile 0 into regs, store to stage 0 ----
    float4 pa0 = *(const float4*)(Ag + (size_t)aRow * K + aCol0);
    float4 pa1 = *(const float4*)(Ag + (size_t)(aRow + 64) * K + aCol0);
    float4 pb0 = *(const float4*)(Bg + (size_t)bRow * N + bCol0);
    float4 pb1 = *(const float4*)(Bg + (size_t)(bRow + 8) * N + bCol0);

    {
        const float av0[4] = {pa0.x, pa0.y, pa0.z, pa0.w};
        const float av1[4] = {pa1.x, pa1.y, pa1.z, pa1.w};
#pragma unroll
        for (int i = 0; i < 4; i++) {
            int k = aCol0 + i;
            unsigned sw = 8u * ((k >> 2) & 3);
            As[0][k][aRow ^ sw]        = f2tf32(av0[i]);
            As[0][k][(aRow + 64) ^ sw] = f2tf32(av1[i]);
        }
        uint4 u0 = {f2tf32(pb0.x), f2tf32(pb0.y), f2tf32(pb0.z), f2tf32(pb0.w)};
        uint4 u1 = {f2tf32(pb1.x), f2tf32(pb1.y), f2tf32(pb1.z), f2tf32(pb1.w)};
        *(uint4*)&Bs[0][bRow][bCol0]     = u0;
        *(uint4*)&Bs[0][bRow + 8][bCol0] = u1;
    }
    __syncthreads();

    for (int t = 0; t < nT; ++t) {
        const int st = t & 1;
        const bool more = (t + 1) < nT;

        // prefetch next tile from gmem
        if (more) {
            int k0 = (t + 1) * 16;
            pa0 = *(const float4*)(Ag + (size_t)aRow * K + k0 + aCol0);
            pa1 = *(const float4*)(Ag + (size_t)(aRow + 64) * K + k0 + aCol0);
            pb0 = *(const float4*)(Bg + (size_t)(k0 + bRow) * N + bCol0);
            pb1 = *(const float4*)(Bg + (size_t)(k0 + bRow + 8) * N + bCol0);
        }

        // compute two k8 steps on stage st
#pragma unroll
        for (int kk = 0; kk < 16; kk += 8) {
            const unsigned s0 = 8u * (((kk) >> 2) & 3);
            const unsigned s1 = 8u * (((kk >> 2) + 1) & 3);

            unsigned af[4][4];
#pragma unroll
            for (int mt = 0; mt < 4; mt++) {
                int mb = warpM + mt * 16 + gid;
                af[mt][0] = As[st][kk + tg][mb ^ s0];
                af[mt][1] = As[st][kk + tg][(mb + 8) ^ s0];
                af[mt][2] = As[st][kk + tg + 4][mb ^ s1];
                af[mt][3] = As[st][kk + tg + 4][(mb + 8) ^ s1];
            }
            unsigned bf[4][2];
#pragma unroll
            for (int nt = 0; nt < 4; nt++) {
                int nb = warpN + nt * 8 + gid;
                bf[nt][0] = Bs[st][kk + tg][nb];
                bf[nt][1] = Bs[st][kk + tg + 4][nb];
            }
#pragma unroll
            for (int mt = 0; mt < 4; mt++)
#pragma unroll
                for (int nt = 0; nt < 4; nt++)
                    mma_tf32(c[mt][nt], af[mt][0], af[mt][1], af[mt][2], af[mt][3],
                             bf[nt][0], bf[nt][1]);
        }

        // store prefetched tile into the other stage
        if (more) {
            const int so = st ^ 1;
            const float av0[4] = {pa0.x, pa0.y, pa0.z, pa0.w};
            const float av1[4] = {pa1.x, pa1.y, pa1.z, pa1.w};
#pragma unroll
            for (int i = 0; i < 4; i++) {
                int k = aCol0 + i;
                unsigned sw = 8u * ((k >> 2) & 3);
                As[so][k][aRow ^ sw]        = f2tf32(av0[i]);
                As[so][k][(aRow + 64) ^ sw] = f2tf32(av1[i]);
            }
            uint4 u0 = {f2tf32(pb0.x), f2tf32(pb0.y), f2tf32(pb0.z), f2tf32(pb0.w)};
            uint4 u1 = {f2tf32(pb1.x), f2tf32(pb1.y), f2tf32(pb1.z), f2tf32(pb1.w)};
            *(uint4*)&Bs[so][bRow][bCol0]     = u0;
            *(uint4*)&Bs[so][bRow + 8][bCol0] = u1;
            __syncthreads();
        }
    }

    // epilogue
#pragma unroll
    for (int mt = 0; mt < 4; mt++) {
        int row = blockRow + warpM + mt * 16 + gid;
#pragma unroll
        for (int nt = 0; nt < 4; nt++) {
            int col = blockCol + warpN + nt * 8 + 2 * tg;
            float b0 = bias ? bias[col] : 0.f;
            float b1 = bias ? bias[col + 1] : 0.f;
            float2 v0 = {c[mt][nt][0] + b0, c[mt][nt][1] + b1};
            float2 v1 = {c[mt][nt][2] + b0, c[mt][nt][3] + b1};
            *(float2*)&C[(size_t)row * N + col]       = v0;
            *(float2*)&C[(size_t)(row + 8) * N + col] = v1;
        }
    }
}

// ---------------------------------------------------------------------------
// Flash attention (fp32, causal, GQA): grid (T/64, H, B), 256 threads.
// ---------------------------------------------------------------------------
__global__ __launch_bounds__(256) void flash_kernel()
{
    extern __shared__ float sm[];
    float* Qs   = sm;                   // [64][132]
    float* Ks   = sm + 64 * 132;        // [64][132]
    float* Vs   = sm + 2 * 64 * 132;    // [64][132]
    float* Ss   = sm + 3 * 64 * 132;    // [64][68]
    float* Mrow = Ss + 64 * 68;         // [64]
    float* Lrow = Mrow + 64;            // [64]
    float* Arow = Lrow + 64;            // [64]

    const int tid  = threadIdx.x;
    const int b    = blockIdx.z;
    const int h    = blockIdx.y;
    const int hkv  = h >> 2;            // G = 4
    const int row0 = blockIdx.x * 64;
    const float scale = 0.08838834764831845f;   // 1/sqrt(128)

    for (int idx = tid; idx < 64 * 32; idx += 256) {
        int r = idx >> 5, d4 = idx & 31;
        float4 q4 = *(const float4*)&g_q[((size_t)(b * SEQ + row0 + r)) * CDIM + h * HD + d4 * 4];
        *(float4*)&Qs[r * 132 + d4 * 4] = q4;
    }
    if (tid < 64) { Mrow[tid] = -1e30f; Lrow[tid] = 0.f; }

    const int ty = tid >> 4, tx = tid & 15;
    const int r0 = ty * 4;

    float o[4][8];
#pragma unroll
    for (int i = 0; i < 4; i++)
#pragma unroll
        for (int j = 0; j < 8; j++) o[i][j] = 0.f;

    const int ntiles = blockIdx.x + 1;
    for (int jt = 0; jt < ntiles; ++jt) {
        const int col0 = jt * 64;
        __syncthreads();

        for (int idx = tid; idx < 64 * 32; idx += 256) {
            int r = idx >> 5, d4 = idx & 31;
            size_t base = ((size_t)(b * SEQ + col0 + r)) * KVC + hkv * HD + d4 * 4;
            *(float4*)&Ks[r * 132 + d4 * 4] = *(const float4*)&g_kv[base];
            *(float4*)&Vs[r * 132 + d4 * 4] = *(const float4*)&g_kv[base + 512];
        }
        __syncthreads();

        float acc[4][4];
#pragma unroll
        for (int i = 0; i < 4; i++)
#pragma unroll
            for (int j = 0; j < 4; j++) acc[i][j] = 0.f;

#pragma unroll 4
        for (int d4 = 0; d4 < 32; ++d4) {
            float4 qf[4], kf[4];
#pragma unroll
            for (int i = 0; i < 4; i++) qf[i] = *(float4*)&Qs[(r0 + i) * 132 + d4 * 4];
#pragma unroll
            for (int j = 0; j < 4; j++) kf[j] = *(float4*)&Ks[(tx + 16 * j) * 132 + d4 * 4];
#pragma unroll
            for (int i = 0; i < 4; i++)
#pragma unroll
                for (int j = 0; j < 4; j++) {
                    acc[i][j] += qf[i].x * kf[j].x;
                    acc[i][j] += qf[i].y * kf[j].y;
                    acc[i][j] += qf[i].z * kf[j].z;
                    acc[i][j] += qf[i].w * kf[j].w;
                }
        }

#pragma unroll
        for (int i = 0; i < 4; i++) {
            int rq = row0 + r0 + i;
#pragma unroll
            for (int j = 0; j < 4; j++) {
                int c = col0 + tx + 16 * j;
                float s = (c <= rq) ? acc[i][j] * scale : -1e30f;
                Ss[(r0 + i) * 68 + tx + 16 * j] = s;
            }
        }
        __syncthreads();

        {
            const int rr = tid >> 2;
            const int c0 = (tid & 3) * 16;
            float mloc = -1e30f;
#pragma unroll
            for (int c = 0; c < 16; c++) mloc = fmaxf(mloc, Ss[rr * 68 + c0 + c]);
            mloc = fmaxf(mloc, __shfl_xor_sync(0xffffffffu, mloc, 1));
            mloc = fmaxf(mloc, __shfl_xor_sync(0xffffffffu, mloc, 2));
            float mold = Mrow[rr];
            float mnew = fmaxf(mold, mloc);
            float lloc = 0.f;
#pragma unroll
            for (int c = 0; c < 16; c++) {
                float p = __expf(Ss[rr * 68 + c0 + c] - mnew);
                Ss[rr * 68 + c0 + c] = p;
                lloc += p;
            }
            lloc += __shfl_xor_sync(0xffffffffu, lloc, 1);
            lloc += __shfl_xor_sync(0xffffffffu, lloc, 2);
            if ((tid & 3) == 0) {
                float alpha = __expf(mold - mnew);
                Mrow[rr] = mnew;
                Lrow[rr] = Lrow[rr] * alpha + lloc;
                Arow[rr] = alpha;
            }
        }
        __syncthreads();

        float al[4];
#pragma unroll
        for (int i = 0; i < 4; i++) al[i] = Arow[r0 + i];
#pragma unroll
        for (int i = 0; i < 4; i++)
#pragma unroll
            for (int jj = 0; jj < 8; jj++) o[i][jj] *= al[i];

#pragma unroll 4
        for (int c = 0; c < 64; ++c) {
            float p0 = Ss[(r0 + 0) * 68 + c];
            float p1 = Ss[(r0 + 1) * 68 + c];
            float p2 = Ss[(r0 + 2) * 68 + c];
            float p3 = Ss[(r0 + 3) * 68 + c];
#pragma unroll
            for (int jj = 0; jj < 8; jj++) {
                float v = Vs[c * 132 + tx + 16 * jj];
                o[0][jj] += p0 * v;
                o[1][jj] += p1 * v;
                o[2][jj] += p2 * v;
                o[3][jj] += p3 * v;
            }
        }
    }

#pragma unroll
    for (int i = 0; i < 4; i++) {
        float linv = 1.f / Lrow[r0 + i];
        size_t base = ((size_t)(b * SEQ + row0 + r0 + i)) * CDIM + h * HD;
#pragma unroll
        for (int jj = 0; jj < 8; jj++)
            g_y[base + tx + 16 * jj] = o[i][jj] * linv;
    }
}

// ---------------------------------------------------------------------------
extern "C" void kernel_launch(void* const* d_in, const int* in_sizes, int n_in,
                              void* d_out, int out_size)
{
    const float* x   = (const float*)d_in[0];
    const float* Wq  = (const float*)d_in[1];
    const float* Wkv = (const float*)d_in[2];
    const float* Wc  = (const float*)d_in[3];
    const float* bc  = (const float*)d_in[4];
    float* out = (float*)d_out;

    float *qb, *kvb, *yb;
    cudaGetSymbolAddress((void**)&qb,  g_q);
    cudaGetSymbolAddress((void**)&kvb, g_kv);
    cudaGetSymbolAddress((void**)&yb,  g_y);

    const int M = BATCH * SEQ;   // 8192
    dim3 blk(256);

    // q = x @ Wq   [8192, 2048]
    gemm_tf32_kernel<<<dim3(CDIM / 128, M / 128), blk>>>(x, Wq, nullptr, qb, M, CDIM, CDIM);
    // kv = x @ Wkv [8192, 1024]
    gemm_tf32_kernel<<<dim3(KVC / 128, M / 128), blk>>>(x, Wkv, nullptr, kvb, M, KVC, CDIM);

    // flash attention
    size_t smem = (size_t)(3 * 64 * 132 + 64 * 68 + 3 * 64) * sizeof(float);
    cudaFuncSetAttribute(flash_kernel, cudaFuncAttributeMaxDynamicSharedMemorySize, (int)smem);
    flash_kernel<<<dim3(SEQ / 64, NH, BATCH), blk, smem>>>();

    // out = y @ Wc + bc
    gemm_tf32_kernel<<<dim3(CDIM / 128, M / 128), blk>>>(yb, Wc, bc, out, M, CDIM, CDIM);
}

// round 8
// speedup vs baseline: 3.4867x; 1.5278x over previous
#include <cuda_runtime.h>
#include <cuda_bf16.h>
#include <math.h>

#define BATCH 4
#define SEQ   2048
#define CDIM  2048
#define NH    16
#define NKV   4
#define HD    128
#define KVC   1024   // 2*NKV*HD

// Scratch (device globals: allocation-free per harness rules)
__device__ float g_q [BATCH * SEQ * CDIM];   // q projection  [B*T, C]
__device__ float g_kv[BATCH * SEQ * KVC];    // kv projection [B*T, 1024]
__device__ float g_y [BATCH * SEQ * CDIM];   // attention out [B*T, C]

__device__ __forceinline__ unsigned f2tf32(float f) {
    unsigned u;
    asm("cvt.rna.tf32.f32 %0, %1;" : "=r"(u) : "f"(f));
    return u;
}

__device__ __forceinline__ void mma_tf32(float c[4],
    unsigned a0, unsigned a1, unsigned a2, unsigned a3,
    unsigned b0, unsigned b1)
{
    asm volatile(
        "mma.sync.aligned.m16n8k8.row.col.f32.tf32.tf32.f32 "
        "{%0,%1,%2,%3}, {%4,%5,%6,%7}, {%8,%9}, {%0,%1,%2,%3};"
        : "+f"(c[0]), "+f"(c[1]), "+f"(c[2]), "+f"(c[3])
        : "r"(a0), "r"(a1), "r"(a2), "r"(a3), "r"(b0), "r"(b1));
}

// ---------------------------------------------------------------------------
// TF32 tensor-core GEMM (unchanged from R6)
// ---------------------------------------------------------------------------
#define GS_AS 136
#define GS_BS 136

__global__ __launch_bounds__(256, 1) void gemm_tf32_kernel(
    const float* __restrict__ A, const float* __restrict__ B,
    const float* __restrict__ bias, float* __restrict__ C,
    int M, int N, int K)
{
    __shared__ unsigned As[2][16][GS_AS];
    __shared__ unsigned Bs[2][16][GS_BS];

    const int tid  = threadIdx.x;
    const int lane = tid & 31;
    const int warp = tid >> 5;
    const int tg   = lane & 3;
    const int gid  = lane >> 2;
    const int warpM = (warp & 1) * 64;
    const int warpN = (warp >> 1) * 32;

    const int blockRow = blockIdx.y * 128;
    const int blockCol = blockIdx.x * 128;

    const int aRow  = tid >> 2;
    const int aCol0 = (tid & 3) * 4;
    const int bRow  = tid >> 5;
    const int bCol0 = (tid & 31) * 4;

    const float* Ag = A + (size_t)(blockRow) * K;
    const float* Bg = B + blockCol;

    float c[4][4][4];
#pragma unroll
    for (int mt = 0; mt < 4; mt++)
#pragma unroll
        for (int nt = 0; nt < 4; nt++)
#pragma unroll
            for (int i = 0; i < 4; i++) c[mt][nt][i] = 0.f;

    const int nT = K / 16;

    float4 pa0 = *(const float4*)(Ag + (size_t)aRow * K + aCol0);
    float4 pa1 = *(const float4*)(Ag + (size_t)(aRow + 64) * K + aCol0);
    float4 pb0 = *(const float4*)(Bg + (size_t)bRow * N + bCol0);
    float4 pb1 = *(const float4*)(Bg + (size_t)(bRow + 8) * N + bCol0);

    {
        const float av0[4] = {pa0.x, pa0.y, pa0.z, pa0.w};
        const float av1[4] = {pa1.x, pa1.y, pa1.z, pa1.w};
#pragma unroll
        for (int i = 0; i < 4; i++) {
            int k = aCol0 + i;
            unsigned sw = 8u * ((k >> 2) & 3);
            As[0][k][aRow ^ sw]        = f2tf32(av0[i]);
            As[0][k][(aRow + 64) ^ sw] = f2tf32(av1[i]);
        }
        uint4 u0 = {f2tf32(pb0.x), f2tf32(pb0.y), f2tf32(pb0.z), f2tf32(pb0.w)};
        uint4 u1 = {f2tf32(pb1.x), f2tf32(pb1.y), f2tf32(pb1.z), f2tf32(pb1.w)};
        *(uint4*)&Bs[0][bRow][bCol0]     = u0;
        *(uint4*)&Bs[0][bRow + 8][bCol0] = u1;
    }
    __syncthreads();

    for (int t = 0; t < nT; ++t) {
        const int st = t & 1;
        const bool more = (t + 1) < nT;

        if (more) {
            int k0 = (t + 1) * 16;
            pa0 = *(const float4*)(Ag + (size_t)aRow * K + k0 + aCol0);
            pa1 = *(const float4*)(Ag + (size_t)(aRow + 64) * K + k0 + aCol0);
            pb0 = *(const float4*)(Bg + (size_t)(k0 + bRow) * N + bCol0);
            pb1 = *(const float4*)(Bg + (size_t)(k0 + bRow + 8) * N + bCol0);
        }

#pragma unroll
        for (int kk = 0; kk < 16; kk += 8) {
            const unsigned s0 = 8u * (((kk) >> 2) & 3);
            const unsigned s1 = 8u * (((kk >> 2) + 1) & 3);

            unsigned af[4][4];
#pragma unroll
            for (int mt = 0; mt < 4; mt++) {
                int mb = warpM + mt * 16 + gid;
                af[mt][0] = As[st][kk + tg][mb ^ s0];
                af[mt][1] = As[st][kk + tg][(mb + 8) ^ s0];
                af[mt][2] = As[st][kk + tg + 4][mb ^ s1];
                af[mt][3] = As[st][kk + tg + 4][(mb + 8) ^ s1];
            }
            unsigned bf[4][2];
#pragma unroll
            for (int nt = 0; nt < 4; nt++) {
                int nb = warpN + nt * 8 + gid;
                bf[nt][0] = Bs[st][kk + tg][nb];
                bf[nt][1] = Bs[st][kk + tg + 4][nb];
            }
#pragma unroll
            for (int mt = 0; mt < 4; mt++)
#pragma unroll
                for (int nt = 0; nt < 4; nt++)
                    mma_tf32(c[mt][nt], af[mt][0], af[mt][1], af[mt][2], af[mt][3],
                             bf[nt][0], bf[nt][1]);
        }

        if (more) {
            const int so = st ^ 1;
            const float av0[4] = {pa0.x, pa0.y, pa0.z, pa0.w};
            const float av1[4] = {pa1.x, pa1.y, pa1.z, pa1.w};
#pragma unroll
            for (int i = 0; i < 4; i++) {
                int k = aCol0 + i;
                unsigned sw = 8u * ((k >> 2) & 3);
                As[so][k][aRow ^ sw]        = f2tf32(av0[i]);
                As[so][k][(aRow + 64) ^ sw] = f2tf32(av1[i]);
            }
            uint4 u0 = {f2tf32(pb0.x), f2tf32(pb0.y), f2tf32(pb0.z), f2tf32(pb0.w)};
            uint4 u1 = {f2tf32(pb1.x), f2tf32(pb1.y), f2tf32(pb1.z), f2tf32(pb1.w)};
            *(uint4*)&Bs[so][bRow][bCol0]     = u0;
            *(uint4*)&Bs[so][bRow + 8][bCol0] = u1;
            __syncthreads();
        }
    }

#pragma unroll
    for (int mt = 0; mt < 4; mt++) {
        int row = blockRow + warpM + mt * 16 + gid;
#pragma unroll
        for (int nt = 0; nt < 4; nt++) {
            int col = blockCol + warpN + nt * 8 + 2 * tg;
            float b0 = bias ? bias[col] : 0.f;
            float b1 = bias ? bias[col + 1] : 0.f;
            float2 v0 = {c[mt][nt][0] + b0, c[mt][nt][1] + b1};
            float2 v1 = {c[mt][nt][2] + b0, c[mt][nt][3] + b1};
            *(float2*)&C[(size_t)row * N + col]       = v0;
            *(float2*)&C[(size_t)(row + 8) * N + col] = v1;
        }
    }
}

// ---------------------------------------------------------------------------
// Flash attention v2: tf32 tensor-core QK^T and PV, fp32 online softmax.
// grid (T/64, H, B), 256 threads (8 warps).
// S phase:  warp layout 4(M) x 2(N): each warp 16 q-rows x 32 kv-cols.
// PV phase: warp layout 4(M) x 2(D): each warp 16 q-rows x 64 d-cols.
// Smem strides (fp32 words): Qs/Ks 132 (=4 mod 32), Vs 136 (=8 mod 32),
// Ss 68 -> all MMA fragment reads bank-conflict-free.
// ---------------------------------------------------------------------------
#define QS_STR 132
#define VS_STR 136
#define SS_STR 68

__global__ __launch_bounds__(256, 1) void flash_kernel()
{
    extern __shared__ unsigned smu[];
    unsigned* Qs = smu;                       // [64][132] tf32
    unsigned* Ks = smu + 64 * QS_STR;         // [64][132] tf32
    unsigned* Vs = smu + 2 * 64 * QS_STR;     // [64][136] tf32
    float*    Ss = (float*)(smu + 2 * 64 * QS_STR + 64 * VS_STR);  // [64][68]
    float* Mrow = Ss + 64 * SS_STR;
    float* Lrow = Mrow + 64;
    float* Arow = Lrow + 64;

    const int tid  = threadIdx.x;
    const int lane = tid & 31;
    const int warp = tid >> 5;
    const int tg   = lane & 3;
    const int gid  = lane >> 2;
    const int wm   = (warp & 3) * 16;     // q-row offset (both phases)
    const int wn   = (warp >> 2) * 32;    // kv-col offset (S phase)
    const int wd   = (warp >> 2) * 64;    // d-col offset (PV phase)

    const int b    = blockIdx.z;
    const int h    = blockIdx.y;
    const int hkv  = h >> 2;              // G = 4
    const int row0 = blockIdx.x * 64;
    const float scale = 0.08838834764831845f;   // 1/sqrt(128)

    // Load Q tile [64][128] -> tf32 smem
    for (int idx = tid; idx < 64 * 32; idx += 256) {
        int r = idx >> 5, d4 = idx & 31;
        float4 q4 = *(const float4*)&g_q[((size_t)(b * SEQ + row0 + r)) * CDIM + h * HD + d4 * 4];
        uint4 u = {f2tf32(q4.x), f2tf32(q4.y), f2tf32(q4.z), f2tf32(q4.w)};
        *(uint4*)&Qs[r * QS_STR + d4 * 4] = u;
    }
    if (tid < 64) { Mrow[tid] = -1e30f; Lrow[tid] = 0.f; }

    float oacc[8][4];
#pragma unroll
    for (int nt = 0; nt < 8; nt++)
#pragma unroll
        for (int i = 0; i < 4; i++) oacc[nt][i] = 0.f;

    const int ntiles = blockIdx.x + 1;     // causal
    for (int jt = 0; jt < ntiles; ++jt) {
        const int col0 = jt * 64;
        const bool diag = (jt == ntiles - 1);
        __syncthreads();   // prev iter done with Ks/Vs/Ss

        // Load K,V tiles -> tf32 smem
        for (int idx = tid; idx < 64 * 32; idx += 256) {
            int r = idx >> 5, d4 = idx & 31;
            size_t base = ((size_t)(b * SEQ + col0 + r)) * KVC + hkv * HD + d4 * 4;
            float4 k4 = *(const float4*)&g_kv[base];
            float4 v4 = *(const float4*)&g_kv[base + 512];
            uint4 ku = {f2tf32(k4.x), f2tf32(k4.y), f2tf32(k4.z), f2tf32(k4.w)};
            uint4 vu = {f2tf32(v4.x), f2tf32(v4.y), f2tf32(v4.z), f2tf32(v4.w)};
            *(uint4*)&Ks[r * QS_STR + d4 * 4] = ku;
            *(uint4*)&Vs[r * VS_STR + d4 * 4] = vu;
        }
        __syncthreads();

        // ---- S = Q @ K^T (tf32 mma) ----
        float sacc[4][4];
#pragma unroll
        for (int nt = 0; nt < 4; nt++)
#pragma unroll
            for (int i = 0; i < 4; i++) sacc[nt][i] = 0.f;

#pragma unroll
        for (int d0 = 0; d0 < HD; d0 += 8) {
            unsigned a0 = Qs[(wm + gid) * QS_STR + d0 + tg];
            unsigned a1 = Qs[(wm + gid + 8) * QS_STR + d0 + tg];
            unsigned a2 = Qs[(wm + gid) * QS_STR + d0 + tg + 4];
            unsigned a3 = Qs[(wm + gid + 8) * QS_STR + d0 + tg + 4];
#pragma unroll
            for (int nt = 0; nt < 4; nt++) {
                int kr = wn + nt * 8 + gid;
                unsigned b0 = Ks[kr * QS_STR + d0 + tg];
                unsigned b1 = Ks[kr * QS_STR + d0 + tg + 4];
                mma_tf32(sacc[nt], a0, a1, a2, a3, b0, b1);
            }
        }

        // scale + mask + store S tile to smem (fp32)
#pragma unroll
        for (int nt = 0; nt < 4; nt++) {
            int colL = wn + nt * 8 + 2 * tg;
            int col_g = col0 + colL;
            int rq0 = row0 + wm + gid;
            int rq1 = rq0 + 8;
            float s0 = sacc[nt][0] * scale;
            float s1 = sacc[nt][1] * scale;
            float s2 = sacc[nt][2] * scale;
            float s3 = sacc[nt][3] * scale;
            if (diag) {
                if (col_g > rq0)     s0 = -1e30f;
                if (col_g + 1 > rq0) s1 = -1e30f;
                if (col_g > rq1)     s2 = -1e30f;
                if (col_g + 1 > rq1) s3 = -1e30f;
            }
            float2 p0 = {s0, s1}, p1 = {s2, s3};
            *(float2*)&Ss[(wm + gid) * SS_STR + colL]     = p0;
            *(float2*)&Ss[(wm + gid + 8) * SS_STR + colL] = p1;
        }
        __syncthreads();

        // ---- online softmax (fp32) ----
        {
            const int rr = tid >> 2;
            const int c0 = (tid & 3) * 16;
            float mloc = -1e30f;
#pragma unroll
            for (int c = 0; c < 16; c++) mloc = fmaxf(mloc, Ss[rr * SS_STR + c0 + c]);
            mloc = fmaxf(mloc, __shfl_xor_sync(0xffffffffu, mloc, 1));
            mloc = fmaxf(mloc, __shfl_xor_sync(0xffffffffu, mloc, 2));
            float mold = Mrow[rr];
            float mnew = fmaxf(mold, mloc);
            float lloc = 0.f;
#pragma unroll
            for (int c = 0; c < 16; c++) {
                float p = __expf(Ss[rr * SS_STR + c0 + c] - mnew);
                Ss[rr * SS_STR + c0 + c] = p;
                lloc += p;
            }
            lloc += __shfl_xor_sync(0xffffffffu, lloc, 1);
            lloc += __shfl_xor_sync(0xffffffffu, lloc, 2);
            if ((tid & 3) == 0) {
                float alpha = __expf(mold - mnew);
                Mrow[rr] = mnew;
                Lrow[rr] = Lrow[rr] * alpha + lloc;
                Arow[rr] = alpha;
            }
        }
        __syncthreads();

        // ---- O = alpha*O + P @ V (tf32 mma) ----
        {
            float al0 = Arow[wm + gid];
            float al1 = Arow[wm + gid + 8];
#pragma unroll
            for (int nt = 0; nt < 8; nt++) {
                oacc[nt][0] *= al0; oacc[nt][1] *= al0;
                oacc[nt][2] *= al1; oacc[nt][3] *= al1;
            }
#pragma unroll
            for (int k0 = 0; k0 < 64; k0 += 8) {
                unsigned a0 = f2tf32(Ss[(wm + gid) * SS_STR + k0 + tg]);
                unsigned a1 = f2tf32(Ss[(wm + gid + 8) * SS_STR + k0 + tg]);
                unsigned a2 = f2tf32(Ss[(wm + gid) * SS_STR + k0 + tg + 4]);
                unsigned a3 = f2tf32(Ss[(wm + gid + 8) * SS_STR + k0 + tg + 4]);
#pragma unroll
                for (int nt = 0; nt < 8; nt++) {
                    int nb = wd + nt * 8 + gid;
                    unsigned b0 = Vs[(k0 + tg) * VS_STR + nb];
                    unsigned b1 = Vs[(k0 + tg + 4) * VS_STR + nb];
                    mma_tf32(oacc[nt], a0, a1, a2, a3, b0, b1);
                }
            }
        }
    }

    // normalize + write out
    {
        float linv0 = 1.f / Lrow[wm + gid];
        float linv1 = 1.f / Lrow[wm + gid + 8];
        size_t r0g = ((size_t)(b * SEQ + row0 + wm + gid)) * CDIM + h * HD;
        size_t r1g = r0g + (size_t)8 * CDIM;
#pragma unroll
        for (int nt = 0; nt < 8; nt++) {
            int col = wd + nt * 8 + 2 * tg;
            float2 v0 = {oacc[nt][0] * linv0, oacc[nt][1] * linv0};
            float2 v1 = {oacc[nt][2] * linv1, oacc[nt][3] * linv1};
            *(float2*)&g_y[r0g + col] = v0;
            *(float2*)&g_y[r1g + col] = v1;
        }
    }
}

// ---------------------------------------------------------------------------
extern "C" void kernel_launch(void* const* d_in, const int* in_sizes, int n_in,
                              void* d_out, int out_size)
{
    const float* x   = (const float*)d_in[0];
    const float* Wq  = (const float*)d_in[1];
    const float* Wkv = (const float*)d_in[2];
    const float* Wc  = (const float*)d_in[3];
    const float* bc  = (const float*)d_in[4];
    float* out = (float*)d_out;

    float *qb, *kvb, *yb;
    cudaGetSymbolAddress((void**)&qb,  g_q);
    cudaGetSymbolAddress((void**)&kvb, g_kv);
    cudaGetSymbolAddress((void**)&yb,  g_y);

    const int M = BATCH * SEQ;   // 8192
    dim3 blk(256);

    gemm_tf32_kernel<<<dim3(CDIM / 128, M / 128), blk>>>(x, Wq, nullptr, qb, M, CDIM, CDIM);
    gemm_tf32_kernel<<<dim3(KVC / 128, M / 128), blk>>>(x, Wkv, nullptr, kvb, M, KVC, CDIM);

    size_t smem = (size_t)(2 * 64 * QS_STR + 64 * VS_STR + 64 * SS_STR + 192) * 4;
    cudaFuncSetAttribute(flash_kernel, cudaFuncAttributeMaxDynamicSharedMemorySize, (int)smem);
    flash_kernel<<<dim3(SEQ / 64, NH, BATCH), blk, smem>>>();

    gemm_tf32_kernel<<<dim3(CDIM / 128, M / 128), blk>>>(yb, Wc, bc, out, M, CDIM, CDIM);
}

// round 10
// speedup vs baseline: 5.1752x; 1.4843x over previous
#include <cuda_runtime.h>
#include <cuda_bf16.h>
#include <math.h>

#define BATCH 4
#define SEQ   2048
#define CDIM  2048
#define NH    16
#define NKV   4
#define HD    128
#define KVC   1024   // 2*NKV*HD

// Scratch (device globals: allocation-free per harness rules)
__device__ float    g_q  [BATCH * SEQ * CDIM];   // q projection  [B*T, C]
__device__ float    g_kv [BATCH * SEQ * KVC];    // kv projection [B*T, 1024]
__device__ float    g_y  [BATCH * SEQ * CDIM];   // attention out [B*T, C]
__device__ unsigned g_xT [CDIM * BATCH * SEQ];   // x^T, tf32 bits  [C][B*T]
__device__ unsigned g_yT [CDIM * BATCH * SEQ];   // y^T, tf32 bits  [C][B*T]
__device__ unsigned g_wq [CDIM * CDIM];          // Wq tf32 bits
__device__ unsigned g_wkv[CDIM * KVC];           // Wkv tf32 bits
__device__ unsigned g_wc [CDIM * CDIM];          // Wc tf32 bits

__device__ __forceinline__ unsigned f2tf32(float f) {
    unsigned u;
    asm("cvt.rna.tf32.f32 %0, %1;" : "=r"(u) : "f"(f));
    return u;
}

__device__ __forceinline__ void mma_tf32(float c[4],
    unsigned a0, unsigned a1, unsigned a2, unsigned a3,
    unsigned b0, unsigned b1)
{
    asm volatile(
        "mma.sync.aligned.m16n8k8.row.col.f32.tf32.tf32.f32 "
        "{%0,%1,%2,%3}, {%4,%5,%6,%7}, {%8,%9}, {%0,%1,%2,%3};"
        : "+f"(c[0]), "+f"(c[1]), "+f"(c[2]), "+f"(c[3])
        : "r"(a0), "r"(a1), "r"(a2), "r"(a3), "r"(b0), "r"(b1));
}

__device__ __forceinline__ void cp16(unsigned smem_u32, const void* gptr) {
    asm volatile("cp.async.cg.shared.global [%0], [%1], 16;" :: "r"(smem_u32), "l"(gptr));
}
__device__ __forceinline__ void cp_commit() {
    asm volatile("cp.async.commit_group;");
}
template<int N>
__device__ __forceinline__ void cp_wait() {
    asm volatile("cp.async.wait_group %0;" :: "n"(N));
}

// ---------------------------------------------------------------------------
// Pre-passes: elementwise tf32 convert, and transpose+convert (32x32 tiles)
// ---------------------------------------------------------------------------
__global__ __launch_bounds__(256) void cvt_kernel(const float* __restrict__ in,
                                                  unsigned* __restrict__ out, int n4)
{
    int i = (blockIdx.x * 256 + threadIdx.x);
    if (i < n4) {
        float4 v = *(const float4*)(in + (size_t)i * 4);
        uint4 u = {f2tf32(v.x), f2tf32(v.y), f2tf32(v.z), f2tf32(v.w)};
        *(uint4*)(out + (size_t)i * 4) = u;
    }
}

// in: [M][N] fp32 -> out: [N][M] tf32 bits
__global__ __launch_bounds__(256) void transpose_cvt_kernel(
    const float* __restrict__ in, unsigned* __restrict__ out, int M, int N)
{
    __shared__ unsigned tile[32][33];
    int x  = blockIdx.x * 32 + threadIdx.x;
    int y0 = blockIdx.y * 32;
#pragma unroll
    for (int j = 0; j < 32; j += 8)
        tile[threadIdx.y + j][threadIdx.x] =
            f2tf32(in[(size_t)(y0 + threadIdx.y + j) * N + x]);
    __syncthreads();
    int xo = y0 + threadIdx.x;                 // col in out
    int yo = blockIdx.x * 32;                  // row base in out
#pragma unroll
    for (int j = 0; j < 32; j += 8)
        out[(size_t)(yo + threadIdx.y + j) * M + xo] = tile[threadIdx.x][threadIdx.y + j];
}

// ---------------------------------------------------------------------------
// TF32 GEMM v2: C[M,N] = A^T(tf32)[K,M] ^T @ B(tf32)[K,N] (+bias)
// 128x128 tile, BK=16, 4-stage cp.async pipeline, 256 thr, 2 CTAs/SM.
// smem: As/Bs [4][16][128] unsigned, XOR granule swizzle g^=2*(k&3).
// Warp layout 2(M) x 4(N) -> 64x32 per warp, m16n8k8.
// ---------------------------------------------------------------------------
#define GSTG 2048              // words per stage per operand (16*128)

__global__ __launch_bounds__(256, 2) void gemm_at_kernel(
    const unsigned* __restrict__ AT, const unsigned* __restrict__ B,
    const float* __restrict__ bias, float* __restrict__ C,
    int M, int N, int K)
{
    extern __shared__ unsigned sh[];           // [0,8K): As  [8K,16K): Bs
    unsigned* AsBase = sh;
    unsigned* BsBase = sh + 4 * GSTG;

    const int tid  = threadIdx.x;
    const int lane = tid & 31;
    const int warp = tid >> 5;
    const int tg   = lane & 3;
    const int gid  = lane >> 2;
    const int warpM = (warp & 1) * 64;
    const int warpN = (warp >> 1) * 32;

    const int blockRow = blockIdx.y * 128;
    const int blockCol = blockIdx.x * 128;

    // copy mapping: 2 granules per operand per thread per stage
    const int k_a  = tid >> 5;                 // for gl = tid     : k 0..7
    const int g_a  = tid & 31;
    const unsigned smem_as = (unsigned)__cvta_generic_to_shared(AsBase);
    const unsigned smem_bs = (unsigned)__cvta_generic_to_shared(BsBase);

    // swizzled fragment column offsets (words within a k-row of 128)
    int colA[4][2], colB[4];
#pragma unroll
    for (int mt = 0; mt < 4; mt++) {
        int mb = warpM + mt * 16 + gid;
        colA[mt][0] = (((mb) >> 2) ^ (2 * tg)) * 4 + (mb & 3);
        int mb8 = mb + 8;
        colA[mt][1] = (((mb8) >> 2) ^ (2 * tg)) * 4 + (mb8 & 3);
    }
#pragma unroll
    for (int nt = 0; nt < 4; nt++) {
        int nb = warpN + nt * 8 + gid;
        colB[nt] = (((nb) >> 2) ^ (2 * tg)) * 4 + (nb & 3);
    }

    float c[4][4][4];
#pragma unroll
    for (int mt = 0; mt < 4; mt++)
#pragma unroll
        for (int nt = 0; nt < 4; nt++)
#pragma unroll
            for (int i = 0; i < 4; i++) c[mt][nt][i] = 0.f;

    const int nT = K / 16;

    // issue one stage's copies
    auto issue = [&](int stage_slot, int k0) {
#pragma unroll
        for (int h = 0; h < 2; h++) {
            int k = k_a + h * 8;
            int g = g_a;
            int gsw = g ^ (2 * (k & 3));
            unsigned dA = smem_as + (stage_slot * GSTG + k * 128 + gsw * 4) * 4u;
            unsigned dB = smem_bs + (stage_slot * GSTG + k * 128 + gsw * 4) * 4u;
            cp16(dA, AT + (size_t)(k0 + k) * M + blockRow + g * 4);
            cp16(dB, B  + (size_t)(k0 + k) * N + blockCol + g * 4);
        }
        cp_commit();
    };

    // prologue: stages 0..2
    issue(0, 0);
    issue(1, 16);
    issue(2, 32);

    for (int t = 0; t < nT; ++t) {
        cp_wait<2>();                  // stage t resident
        __syncthreads();

        int nxt = t + 3;
        if (nxt < nT) issue(nxt & 3, nxt * 16);

        const int st = t & 3;
        const unsigned* As = AsBase + st * GSTG;
        const unsigned* Bs = BsBase + st * GSTG;

#pragma unroll
        for (int kk = 0; kk < 16; kk += 8) {
            const unsigned* a0r = As + (kk + tg) * 128;
            const unsigned* a1r = a0r + 4 * 128;
            const unsigned* b0r = Bs + (kk + tg) * 128;
            const unsigned* b1r = b0r + 4 * 128;

            unsigned af[4][4];
#pragma unroll
            for (int mt = 0; mt < 4; mt++) {
                af[mt][0] = a0r[colA[mt][0]];
                af[mt][1] = a0r[colA[mt][1]];
                af[mt][2] = a1r[colA[mt][0]];
                af[mt][3] = a1r[colA[mt][1]];
            }
            unsigned bf[4][2];
#pragma unroll
            for (int nt = 0; nt < 4; nt++) {
                bf[nt][0] = b0r[colB[nt]];
                bf[nt][1] = b1r[colB[nt]];
            }
#pragma unroll
            for (int mt = 0; mt < 4; mt++)
#pragma unroll
                for (int nt = 0; nt < 4; nt++)
                    mma_tf32(c[mt][nt], af[mt][0], af[mt][1], af[mt][2], af[mt][3],
                             bf[nt][0], bf[nt][1]);
        }
        __syncthreads();               // done reading slot st before it is refilled
    }

    // epilogue
#pragma unroll
    for (int mt = 0; mt < 4; mt++) {
        int row = blockRow + warpM + mt * 16 + gid;
#pragma unroll
        for (int nt = 0; nt < 4; nt++) {
            int col = blockCol + warpN + nt * 8 + 2 * tg;
            float b0 = bias ? bias[col] : 0.f;
            float b1 = bias ? bias[col + 1] : 0.f;
            float2 v0 = {c[mt][nt][0] + b0, c[mt][nt][1] + b1};
            float2 v1 = {c[mt][nt][2] + b0, c[mt][nt][3] + b1};
            *(float2*)&C[(size_t)row * N + col]       = v0;
            *(float2*)&C[(size_t)(row + 8) * N + col] = v1;
        }
    }
}

// ---------------------------------------------------------------------------
// Flash attention (tf32 mma + fp32 online softmax) — unchanged from R8
// ---------------------------------------------------------------------------
#define QS_STR 132
#define VS_STR 136
#define SS_STR 68

__global__ __launch_bounds__(256, 1) void flash_kernel()
{
    extern __shared__ unsigned smu[];
    unsigned* Qs = smu;
    unsigned* Ks = smu + 64 * QS_STR;
    unsigned* Vs = smu + 2 * 64 * QS_STR;
    float*    Ss = (float*)(smu + 2 * 64 * QS_STR + 64 * VS_STR);
    float* Mrow = Ss + 64 * SS_STR;
    float* Lrow = Mrow + 64;
    float* Arow = Lrow + 64;

    const int tid  = threadIdx.x;
    const int lane = tid & 31;
    const int warp = tid >> 5;
    const int tg   = lane & 3;
    const int gid  = lane >> 2;
    const int wm   = (warp & 3) * 16;
    const int wn   = (warp >> 2) * 32;
    const int wd   = (warp >> 2) * 64;

    const int b    = blockIdx.z;
    const int h    = blockIdx.y;
    const int hkv  = h >> 2;
    const int row0 = blockIdx.x * 64;
    const float scale = 0.08838834764831845f;

    for (int idx = tid; idx < 64 * 32; idx += 256) {
        int r = idx >> 5, d4 = idx & 31;
        float4 q4 = *(const float4*)&g_q[((size_t)(b * SEQ + row0 + r)) * CDIM + h * HD + d4 * 4];
        uint4 u = {f2tf32(q4.x), f2tf32(q4.y), f2tf32(q4.z), f2tf32(q4.w)};
        *(uint4*)&Qs[r * QS_STR + d4 * 4] = u;
    }
    if (tid < 64) { Mrow[tid] = -1e30f; Lrow[tid] = 0.f; }

    float oacc[8][4];
#pragma unroll
    for (int nt = 0; nt < 8; nt++)
#pragma unroll
        for (int i = 0; i < 4; i++) oacc[nt][i] = 0.f;

    const int ntiles = blockIdx.x + 1;
    for (int jt = 0; jt < ntiles; ++jt) {
        const int col0 = jt * 64;
        const bool diag = (jt == ntiles - 1);
        __syncthreads();

        for (int idx = tid; idx < 64 * 32; idx += 256) {
            int r = idx >> 5, d4 = idx & 31;
            size_t base = ((size_t)(b * SEQ + col0 + r)) * KVC + hkv * HD + d4 * 4;
            float4 k4 = *(const float4*)&g_kv[base];
            float4 v4 = *(const float4*)&g_kv[base + 512];
            uint4 ku = {f2tf32(k4.x), f2tf32(k4.y), f2tf32(k4.z), f2tf32(k4.w)};
            uint4 vu = {f2tf32(v4.x), f2tf32(v4.y), f2tf32(v4.z), f2tf32(v4.w)};
            *(uint4*)&Ks[r * QS_STR + d4 * 4] = ku;
            *(uint4*)&Vs[r * VS_STR + d4 * 4] = vu;
        }
        __syncthreads();

        float sacc[4][4];
#pragma unroll
        for (int nt = 0; nt < 4; nt++)
#pragma unroll
            for (int i = 0; i < 4; i++) sacc[nt][i] = 0.f;

#pragma unroll
        for (int d0 = 0; d0 < HD; d0 += 8) {
            unsigned a0 = Qs[(wm + gid) * QS_STR + d0 + tg];
            unsigned a1 = Qs[(wm + gid + 8) * QS_STR + d0 + tg];
            unsigned a2 = Qs[(wm + gid) * QS_STR + d0 + tg + 4];
            unsigned a3 = Qs[(wm + gid + 8) * QS_STR + d0 + tg + 4];
#pragma unroll
            for (int nt = 0; nt < 4; nt++) {
                int kr = wn + nt * 8 + gid;
                unsigned b0 = Ks[kr * QS_STR + d0 + tg];
                unsigned b1 = Ks[kr * QS_STR + d0 + tg + 4];
                mma_tf32(sacc[nt], a0, a1, a2, a3, b0, b1);
            }
        }

#pragma unroll
        for (int nt = 0; nt < 4; nt++) {
            int colL = wn + nt * 8 + 2 * tg;
            int col_g = col0 + colL;
            int rq0 = row0 + wm + gid;
            int rq1 = rq0 + 8;
            float s0 = sacc[nt][0] * scale;
            float s1 = sacc[nt][1] * scale;
            float s2 = sacc[nt][2] * scale;
            float s3 = sacc[nt][3] * scale;
            if (diag) {
                if (col_g > rq0)     s0 = -1e30f;
                if (col_g + 1 > rq0) s1 = -1e30f;
                if (col_g > rq1)     s2 = -1e30f;
                if (col_g + 1 > rq1) s3 = -1e30f;
            }
            float2 p0 = {s0, s1}, p1 = {s2, s3};
            *(float2*)&Ss[(wm + gid) * SS_STR + colL]     = p0;
            *(float2*)&Ss[(wm + gid + 8) * SS_STR + colL] = p1;
        }
        __syncthreads();

        {
            const int rr = tid >> 2;
            const int c0 = (tid & 3) * 16;
            float mloc = -1e30f;
#pragma unroll
            for (int c = 0; c < 16; c++) mloc = fmaxf(mloc, Ss[rr * SS_STR + c0 + c]);
            mloc = fmaxf(mloc, __shfl_xor_sync(0xffffffffu, mloc, 1));
            mloc = fmaxf(mloc, __shfl_xor_sync(0xffffffffu, mloc, 2));
            float mold = Mrow[rr];
            float mnew = fmaxf(mold, mloc);
            float lloc = 0.f;
#pragma unroll
            for (int c = 0; c < 16; c++) {
                float p = __expf(Ss[rr * SS_STR + c0 + c] - mnew);
                Ss[rr * SS_STR + c0 + c] = p;
                lloc += p;
            }
            lloc += __shfl_xor_sync(0xffffffffu, lloc, 1);
            lloc += __shfl_xor_sync(0xffffffffu, lloc, 2);
            if ((tid & 3) == 0) {
                float alpha = __expf(mold - mnew);
                Mrow[rr] = mnew;
                Lrow[rr] = Lrow[rr] * alpha + lloc;
                Arow[rr] = alpha;
            }
        }
        __syncthreads();

        {
            float al0 = Arow[wm + gid];
            float al1 = Arow[wm + gid + 8];
#pragma unroll
            for (int nt = 0; nt < 8; nt++) {
                oacc[nt][0] *= al0; oacc[nt][1] *= al0;
                oacc[nt][2] *= al1; oacc[nt][3] *= al1;
            }
#pragma unroll
            for (int k0 = 0; k0 < 64; k0 += 8) {
                unsigned a0 = f2tf32(Ss[(wm + gid) * SS_STR + k0 + tg]);
                unsigned a1 = f2tf32(Ss[(wm + gid + 8) * SS_STR + k0 + tg]);
                unsigned a2 = f2tf32(Ss[(wm + gid) * SS_STR + k0 + tg + 4]);
                unsigned a3 = f2tf32(Ss[(wm + gid + 8) * SS_STR + k0 + tg + 4]);
#pragma unroll
                for (int nt = 0; nt < 8; nt++) {
                    int nb = wd + nt * 8 + gid;
                    unsigned b0 = Vs[(k0 + tg) * VS_STR + nb];
                    unsigned b1 = Vs[(k0 + tg + 4) * VS_STR + nb];
                    mma_tf32(oacc[nt], a0, a1, a2, a3, b0, b1);
                }
            }
        }
    }

    {
        float linv0 = 1.f / Lrow[wm + gid];
        float linv1 = 1.f / Lrow[wm + gid + 8];
        size_t r0g = ((size_t)(b * SEQ + row0 + wm + gid)) * CDIM + h * HD;
        size_t r1g = r0g + (size_t)8 * CDIM;
#pragma unroll
        for (int nt = 0; nt < 8; nt++) {
            int col = wd + nt * 8 + 2 * tg;
            float2 v0 = {oacc[nt][0] * linv0, oacc[nt][1] * linv0};
            float2 v1 = {oacc[nt][2] * linv1, oacc[nt][3] * linv1};
            *(float2*)&g_y[r0g + col] = v0;
            *(float2*)&g_y[r1g + col] = v1;
        }
    }
}

// ---------------------------------------------------------------------------
extern "C" void kernel_launch(void* const* d_in, const int* in_sizes, int n_in,
                              void* d_out, int out_size)
{
    const float* x   = (const float*)d_in[0];
    const float* Wq  = (const float*)d_in[1];
    const float* Wkv = (const float*)d_in[2];
    const float* Wc  = (const float*)d_in[3];
    const float* bc  = (const float*)d_in[4];
    float* out = (float*)d_out;

    float *qb, *kvb, *yb;
    unsigned *xT, *yT, *wq, *wkv, *wc;
    cudaGetSymbolAddress((void**)&qb,  g_q);
    cudaGetSymbolAddress((void**)&kvb, g_kv);
    cudaGetSymbolAddress((void**)&yb,  g_y);
    cudaGetSymbolAddress((void**)&xT,  g_xT);
    cudaGetSymbolAddress((void**)&yT,  g_yT);
    cudaGetSymbolAddress((void**)&wq,  g_wq);
    cudaGetSymbolAddress((void**)&wkv, g_wkv);
    cudaGetSymbolAddress((void**)&wc,  g_wc);

    const int M = BATCH * SEQ;   // 8192
    dim3 blk(256);

    // --- pre-passes: convert weights, transpose+convert x ---
    cvt_kernel<<<(CDIM * CDIM / 4 + 255) / 256, blk>>>(Wq,  wq,  CDIM * CDIM / 4);
    cvt_kernel<<<(CDIM * KVC  / 4 + 255) / 256, blk>>>(Wkv, wkv, CDIM * KVC / 4);
    cvt_kernel<<<(CDIM * CDIM / 4 + 255) / 256, blk>>>(Wc,  wc,  CDIM * CDIM / 4);
    transpose_cvt_kernel<<<dim3(CDIM / 32, M / 32), dim3(32, 8)>>>(x, xT, M, CDIM);

    // --- projections ---
    size_t gsm = (size_t)8 * GSTG * 4;   // 64 KB
    cudaFuncSetAttribute(gemm_at_kernel, cudaFuncAttributeMaxDynamicSharedMemorySize, (int)gsm);
    gemm_at_kernel<<<dim3(CDIM / 128, M / 128), blk, gsm>>>(xT, wq,  nullptr, qb,  M, CDIM, CDIM);
    gemm_at_kernel<<<dim3(KVC  / 128, M / 128), blk, gsm>>>(xT, wkv, nullptr, kvb, M, KVC, CDIM);

    // --- flash attention ---
    size_t smem = (size_t)(2 * 64 * QS_STR + 64 * VS_STR + 64 * SS_STR + 192) * 4;
    cudaFuncSetAttribute(flash_kernel, cudaFuncAttributeMaxDynamicSharedMemorySize, (int)smem);
    flash_kernel<<<dim3(SEQ / 64, NH, BATCH), blk, smem>>>();

    // --- output projection ---
    transpose_cvt_kernel<<<dim3(CDIM / 32, M / 32), dim3(32, 8)>>>(yb, yT, M, CDIM);
    gemm_at_kernel<<<dim3(CDIM / 128, M / 128), blk, gsm>>>(yT, wc, bc, out, M, CDIM, CDIM);
}

// round 11
// speedup vs baseline: 5.4643x; 1.0559x over previous
#include <cuda_runtime.h>
#include <cuda_bf16.h>
#include <math.h>

#define BATCH 4
#define SEQ   2048
#define CDIM  2048
#define NH    16
#define NKV   4
#define HD    128
#define KVC   1024   // 2*NKV*HD

// Scratch (device globals: allocation-free per harness rules)
__device__ unsigned g_q  [BATCH * SEQ * CDIM];   // q projection, tf32 bits
__device__ unsigned g_kv [BATCH * SEQ * KVC];    // kv projection, tf32 bits
__device__ float    g_y  [BATCH * SEQ * CDIM];   // attention out [B*T, C]
__device__ unsigned g_xT [CDIM * BATCH * SEQ];   // x^T, tf32 bits  [C][B*T]
__device__ unsigned g_yT [CDIM * BATCH * SEQ];   // y^T, tf32 bits  [C][B*T]
__device__ unsigned g_wq [CDIM * CDIM];          // Wq tf32 bits
__device__ unsigned g_wkv[CDIM * KVC];           // Wkv tf32 bits
__device__ unsigned g_wc [CDIM * CDIM];          // Wc tf32 bits

__device__ __forceinline__ unsigned f2tf32(float f) {
    unsigned u;
    asm("cvt.rna.tf32.f32 %0, %1;" : "=r"(u) : "f"(f));
    return u;
}

__device__ __forceinline__ void mma_tf32(float c[4],
    unsigned a0, unsigned a1, unsigned a2, unsigned a3,
    unsigned b0, unsigned b1)
{
    asm volatile(
        "mma.sync.aligned.m16n8k8.row.col.f32.tf32.tf32.f32 "
        "{%0,%1,%2,%3}, {%4,%5,%6,%7}, {%8,%9}, {%0,%1,%2,%3};"
        : "+f"(c[0]), "+f"(c[1]), "+f"(c[2]), "+f"(c[3])
        : "r"(a0), "r"(a1), "r"(a2), "r"(a3), "r"(b0), "r"(b1));
}

__device__ __forceinline__ void cp16(unsigned smem_u32, const void* gptr) {
    asm volatile("cp.async.cg.shared.global [%0], [%1], 16;" :: "r"(smem_u32), "l"(gptr));
}
__device__ __forceinline__ void cp_commit() {
    asm volatile("cp.async.commit_group;");
}
template<int N>
__device__ __forceinline__ void cp_wait() {
    asm volatile("cp.async.wait_group %0;" :: "n"(N));
}

// ---------------------------------------------------------------------------
// Pre-passes
// ---------------------------------------------------------------------------
__global__ __launch_bounds__(256) void cvt_kernel(const float* __restrict__ in,
                                                  unsigned* __restrict__ out, int n4)
{
    int i = (blockIdx.x * 256 + threadIdx.x);
    if (i < n4) {
        float4 v = *(const float4*)(in + (size_t)i * 4);
        uint4 u = {f2tf32(v.x), f2tf32(v.y), f2tf32(v.z), f2tf32(v.w)};
        *(uint4*)(out + (size_t)i * 4) = u;
    }
}

// in: [M][N] fp32 -> out: [N][M] tf32 bits
__global__ __launch_bounds__(256) void transpose_cvt_kernel(
    const float* __restrict__ in, unsigned* __restrict__ out, int M, int N)
{
    __shared__ unsigned tile[32][33];
    int x  = blockIdx.x * 32 + threadIdx.x;
    int y0 = blockIdx.y * 32;
#pragma unroll
    for (int j = 0; j < 32; j += 8)
        tile[threadIdx.y + j][threadIdx.x] =
            f2tf32(in[(size_t)(y0 + threadIdx.y + j) * N + x]);
    __syncthreads();
    int xo = y0 + threadIdx.x;
    int yo = blockIdx.x * 32;
#pragma unroll
    for (int j = 0; j < 32; j += 8)
        out[(size_t)(yo + threadIdx.y + j) * M + xo] = tile[threadIdx.x][threadIdx.y + j];
}

// ---------------------------------------------------------------------------
// TF32 GEMM: C[M,N] = A^T(tf32)[K,M] ^T @ B(tf32)[K,N] (+bias)
// 128x128 tile, BK=16, 4-stage cp.async, 256 thr, 2 CTAs/SM.
// TF32OUT: store result as tf32 bits (for q/kv feeding flash) vs fp32.
// ---------------------------------------------------------------------------
#define GSTG 2048              // words per stage per operand (16*128)

template<bool TF32OUT>
__global__ __launch_bounds__(256, 2) void gemm_at_kernel(
    const unsigned* __restrict__ AT, const unsigned* __restrict__ B,
    const float* __restrict__ bias, void* __restrict__ Cv,
    int M, int N, int K)
{
    extern __shared__ unsigned sh[];
    unsigned* AsBase = sh;
    unsigned* BsBase = sh + 4 * GSTG;

    const int tid  = threadIdx.x;
    const int lane = tid & 31;
    const int warp = tid >> 5;
    const int tg   = lane & 3;
    const int gid  = lane >> 2;
    const int warpM = (warp & 1) * 64;
    const int warpN = (warp >> 1) * 32;

    const int blockRow = blockIdx.y * 128;
    const int blockCol = blockIdx.x * 128;

    const int k_a  = tid >> 5;
    const int g_a  = tid & 31;
    const unsigned smem_as = (unsigned)__cvta_generic_to_shared(AsBase);
    const unsigned smem_bs = (unsigned)__cvta_generic_to_shared(BsBase);

    int colA[4][2], colB[4];
#pragma unroll
    for (int mt = 0; mt < 4; mt++) {
        int mb = warpM + mt * 16 + gid;
        colA[mt][0] = (((mb) >> 2) ^ (2 * tg)) * 4 + (mb & 3);
        int mb8 = mb + 8;
        colA[mt][1] = (((mb8) >> 2) ^ (2 * tg)) * 4 + (mb8 & 3);
    }
#pragma unroll
    for (int nt = 0; nt < 4; nt++) {
        int nb = warpN + nt * 8 + gid;
        colB[nt] = (((nb) >> 2) ^ (2 * tg)) * 4 + (nb & 3);
    }

    float c[4][4][4];
#pragma unroll
    for (int mt = 0; mt < 4; mt++)
#pragma unroll
        for (int nt = 0; nt < 4; nt++)
#pragma unroll
            for (int i = 0; i < 4; i++) c[mt][nt][i] = 0.f;

    const int nT = K / 16;

    auto issue = [&](int stage_slot, int k0) {
#pragma unroll
        for (int h = 0; h < 2; h++) {
            int k = k_a + h * 8;
            int g = g_a;
            int gsw = g ^ (2 * (k & 3));
            unsigned dA = smem_as + (stage_slot * GSTG + k * 128 + gsw * 4) * 4u;
            unsigned dB = smem_bs + (stage_slot * GSTG + k * 128 + gsw * 4) * 4u;
            cp16(dA, AT + (size_t)(k0 + k) * M + blockRow + g * 4);
            cp16(dB, B  + (size_t)(k0 + k) * N + blockCol + g * 4);
        }
        cp_commit();
    };

    issue(0, 0);
    issue(1, 16);
    issue(2, 32);

    for (int t = 0; t < nT; ++t) {
        cp_wait<2>();
        __syncthreads();

        int nxt = t + 3;
        if (nxt < nT) issue(nxt & 3, nxt * 16);

        const int st = t & 3;
        const unsigned* As = AsBase + st * GSTG;
        const unsigned* Bs = BsBase + st * GSTG;

#pragma unroll
        for (int kk = 0; kk < 16; kk += 8) {
            const unsigned* a0r = As + (kk + tg) * 128;
            const unsigned* a1r = a0r + 4 * 128;
            const unsigned* b0r = Bs + (kk + tg) * 128;
            const unsigned* b1r = b0r + 4 * 128;

            unsigned af[4][4];
#pragma unroll
            for (int mt = 0; mt < 4; mt++) {
                af[mt][0] = a0r[colA[mt][0]];
                af[mt][1] = a0r[colA[mt][1]];
                af[mt][2] = a1r[colA[mt][0]];
                af[mt][3] = a1r[colA[mt][1]];
            }
            unsigned bf[4][2];
#pragma unroll
            for (int nt = 0; nt < 4; nt++) {
                bf[nt][0] = b0r[colB[nt]];
                bf[nt][1] = b1r[colB[nt]];
            }
#pragma unroll
            for (int mt = 0; mt < 4; mt++)
#pragma unroll
                for (int nt = 0; nt < 4; nt++)
                    mma_tf32(c[mt][nt], af[mt][0], af[mt][1], af[mt][2], af[mt][3],
                             bf[nt][0], bf[nt][1]);
        }
        __syncthreads();
    }

#pragma unroll
    for (int mt = 0; mt < 4; mt++) {
        int row = blockRow + warpM + mt * 16 + gid;
#pragma unroll
        for (int nt = 0; nt < 4; nt++) {
            int col = blockCol + warpN + nt * 8 + 2 * tg;
            float b0 = bias ? bias[col] : 0.f;
            float b1 = bias ? bias[col + 1] : 0.f;
            float v00 = c[mt][nt][0] + b0, v01 = c[mt][nt][1] + b1;
            float v10 = c[mt][nt][2] + b0, v11 = c[mt][nt][3] + b1;
            if (TF32OUT) {
                unsigned* C = (unsigned*)Cv;
                uint2 u0 = {f2tf32(v00), f2tf32(v01)};
                uint2 u1 = {f2tf32(v10), f2tf32(v11)};
                *(uint2*)&C[(size_t)row * N + col]       = u0;
                *(uint2*)&C[(size_t)(row + 8) * N + col] = u1;
            } else {
                float* C = (float*)Cv;
                float2 f0 = {v00, v01};
                float2 f1 = {v10, v11};
                *(float2*)&C[(size_t)row * N + col]       = f0;
                *(float2*)&C[(size_t)(row + 8) * N + col] = f1;
            }
        }
    }
}

// ---------------------------------------------------------------------------
// Flash attention v3: tf32 operands direct from gmem (no cvt), cp.async
// double-buffered K/V, fp32 online softmax, P stored as tf32 bits.
// grid (T/64, H, B), 256 threads (8 warps).
// ---------------------------------------------------------------------------
#define QS_STR 132
#define VS_STR 136
#define PS_STR 68

#define KS_BUF 8448            // 64*132 words per K buffer
#define VS_BUF 8704            // 64*136 words per V buffer

__global__ __launch_bounds__(256, 1) void flash_kernel()
{
    extern __shared__ unsigned smu[];
    unsigned* Qs  = smu;                            // [64][132]
    unsigned* Ks0 = smu + 8448;                     // [2][64][132]
    unsigned* Vs0 = smu + 8448 + 2 * KS_BUF;        // [2][64][136]
    unsigned* Ps  = smu + 8448 + 2 * KS_BUF + 2 * VS_BUF;   // [64][68] S fp32 then P tf32
    float* Sf   = (float*)Ps;
    float* Mrow = (float*)(Ps + 64 * PS_STR);
    float* Lrow = Mrow + 64;
    float* Arow = Lrow + 64;

    const int tid  = threadIdx.x;
    const int lane = tid & 31;
    const int warp = tid >> 5;
    const int tg   = lane & 3;
    const int gid  = lane >> 2;
    const int wm   = (warp & 3) * 16;
    const int wn   = (warp >> 2) * 32;
    const int wd   = (warp >> 2) * 64;

    const int b    = blockIdx.z;
    const int h    = blockIdx.y;
    const int hkv  = h >> 2;
    const int row0 = blockIdx.x * 64;
    const float scale = 0.08838834764831845f;

    const unsigned smem_base = (unsigned)__cvta_generic_to_shared(smu);

    // issue cp.async loads for kv tile jt2 into buffer jt2&1
    auto issue = [&](int jt2) {
        const int bf = jt2 & 1;
        const int col0 = jt2 * 64;
        const unsigned kbase = smem_base + (8448 + bf * KS_BUF) * 4u;
        const unsigned vbase = smem_base + (8448 + 2 * KS_BUF + bf * VS_BUF) * 4u;
#pragma unroll
        for (int i = 0; i < 8; i++) {
            int g = tid + i * 256;            // 0..2047
            int r = g >> 5, d4 = g & 31;
            const unsigned* src = g_kv + ((size_t)(b * SEQ + col0 + r)) * KVC + hkv * HD + d4 * 4;
            cp16(kbase + (r * QS_STR + d4 * 4) * 4u, src);
            cp16(vbase + (r * VS_STR + d4 * 4) * 4u, src + 512);
        }
        cp_commit();
    };

    // Load Q tile (tf32 bits, no conversion)
    for (int idx = tid; idx < 64 * 32; idx += 256) {
        int r = idx >> 5, d4 = idx & 31;
        uint4 u = *(const uint4*)&g_q[((size_t)(b * SEQ + row0 + r)) * CDIM + h * HD + d4 * 4];
        *(uint4*)&Qs[r * QS_STR + d4 * 4] = u;
    }
    if (tid < 64) { Mrow[tid] = -1e30f; Lrow[tid] = 0.f; }

    float oacc[8][4];
#pragma unroll
    for (int nt = 0; nt < 8; nt++)
#pragma unroll
        for (int i = 0; i < 4; i++) oacc[nt][i] = 0.f;

    const int ntiles = blockIdx.x + 1;
    issue(0);

    for (int jt = 0; jt < ntiles; ++jt) {
        const int col0 = jt * 64;
        const bool diag = (jt == ntiles - 1);
        const int bf = jt & 1;
        const unsigned* Ks = Ks0 + bf * KS_BUF;
        const unsigned* Vs = Vs0 + bf * VS_BUF;

        cp_wait<0>();          // tile jt resident (only group in flight)
        __syncthreads();       // all warps past prior reads of both buffers

        if (jt + 1 < ntiles) issue(jt + 1);   // overlaps with compute below

        // ---- S = Q @ K^T ----
        float sacc[4][4];
#pragma unroll
        for (int nt = 0; nt < 4; nt++)
#pragma unroll
            for (int i = 0; i < 4; i++) sacc[nt][i] = 0.f;

#pragma unroll
        for (int d0 = 0; d0 < HD; d0 += 8) {
            unsigned a0 = Qs[(wm + gid) * QS_STR + d0 + tg];
            unsigned a1 = Qs[(wm + gid + 8) * QS_STR + d0 + tg];
            unsigned a2 = Qs[(wm + gid) * QS_STR + d0 + tg + 4];
            unsigned a3 = Qs[(wm + gid + 8) * QS_STR + d0 + tg + 4];
#pragma unroll
            for (int nt = 0; nt < 4; nt++) {
                int kr = wn + nt * 8 + gid;
                unsigned b0 = Ks[kr * QS_STR + d0 + tg];
                unsigned b1 = Ks[kr * QS_STR + d0 + tg + 4];
                mma_tf32(sacc[nt], a0, a1, a2, a3, b0, b1);
            }
        }

        // scale + mask + store S (fp32)
#pragma unroll
        for (int nt = 0; nt < 4; nt++) {
            int colL = wn + nt * 8 + 2 * tg;
            int col_g = col0 + colL;
            int rq0 = row0 + wm + gid;
            int rq1 = rq0 + 8;
            float s0 = sacc[nt][0] * scale;
            float s1 = sacc[nt][1] * scale;
            float s2 = sacc[nt][2] * scale;
            float s3 = sacc[nt][3] * scale;
            if (diag) {
                if (col_g > rq0)     s0 = -1e30f;
                if (col_g + 1 > rq0) s1 = -1e30f;
                if (col_g > rq1)     s2 = -1e30f;
                if (col_g + 1 > rq1) s3 = -1e30f;
            }
            float2 p0 = {s0, s1}, p1 = {s2, s3};
            *(float2*)&Sf[(wm + gid) * PS_STR + colL]     = p0;
            *(float2*)&Sf[(wm + gid + 8) * PS_STR + colL] = p1;
        }
        __syncthreads();

        // ---- online softmax; write P as tf32 bits ----
        {
            const int rr = tid >> 2;
            const int c0 = (tid & 3) * 16;
            float mloc = -1e30f;
#pragma unroll
            for (int c = 0; c < 16; c++) mloc = fmaxf(mloc, Sf[rr * PS_STR + c0 + c]);
            mloc = fmaxf(mloc, __shfl_xor_sync(0xffffffffu, mloc, 1));
            mloc = fmaxf(mloc, __shfl_xor_sync(0xffffffffu, mloc, 2));
            float mold = Mrow[rr];
            float mnew = fmaxf(mold, mloc);
            float lloc = 0.f;
#pragma unroll
            for (int c = 0; c < 16; c++) {
                float p = __expf(Sf[rr * PS_STR + c0 + c] - mnew);
                Ps[rr * PS_STR + c0 + c] = f2tf32(p);
                lloc += p;
            }
            lloc += __shfl_xor_sync(0xffffffffu, lloc, 1);
            lloc += __shfl_xor_sync(0xffffffffu, lloc, 2);
            if ((tid & 3) == 0) {
                float alpha = __expf(mold - mnew);
                Mrow[rr] = mnew;
                Lrow[rr] = Lrow[rr] * alpha + lloc;
                Arow[rr] = alpha;
            }
        }
        __syncthreads();

        // ---- O = alpha*O + P @ V ----
        {
            float al0 = Arow[wm + gid];
            float al1 = Arow[wm + gid + 8];
#pragma unroll
            for (int nt = 0; nt < 8; nt++) {
                oacc[nt][0] *= al0; oacc[nt][1] *= al0;
                oacc[nt][2] *= al1; oacc[nt][3] *= al1;
            }
#pragma unroll
            for (int k0 = 0; k0 < 64; k0 += 8) {
                unsigned a0 = Ps[(wm + gid) * PS_STR + k0 + tg];
                unsigned a1 = Ps[(wm + gid + 8) * PS_STR + k0 + tg];
                unsigned a2 = Ps[(wm + gid) * PS_STR + k0 + tg + 4];
                unsigned a3 = Ps[(wm + gid + 8) * PS_STR + k0 + tg + 4];
#pragma unroll
                for (int nt = 0; nt < 8; nt++) {
                    int nb = wd + nt * 8 + gid;
                    unsigned b0 = Vs[(k0 + tg) * VS_STR + nb];
                    unsigned b1 = Vs[(k0 + tg + 4) * VS_STR + nb];
                    mma_tf32(oacc[nt], a0, a1, a2, a3, b0, b1);
                }
            }
        }
    }

    // normalize + write out
    {
        float linv0 = 1.f / Lrow[wm + gid];
        float linv1 = 1.f / Lrow[wm + gid + 8];
        size_t r0g = ((size_t)(b * SEQ + row0 + wm + gid)) * CDIM + h * HD;
        size_t r1g = r0g + (size_t)8 * CDIM;
#pragma unroll
        for (int nt = 0; nt < 8; nt++) {
            int col = wd + nt * 8 + 2 * tg;
            float2 v0 = {oacc[nt][0] * linv0, oacc[nt][1] * linv0};
            float2 v1 = {oacc[nt][2] * linv1, oacc[nt][3] * linv1};
            *(float2*)&g_y[r0g + col] = v0;
            *(float2*)&g_y[r1g + col] = v1;
        }
    }
}

// ---------------------------------------------------------------------------
extern "C" void kernel_launch(void* const* d_in, const int* in_sizes, int n_in,
                              void* d_out, int out_size)
{
    const float* x   = (const float*)d_in[0];
    const float* Wq  = (const float*)d_in[1];
    const float* Wkv = (const float*)d_in[2];
    const float* Wc  = (const float*)d_in[3];
    const float* bc  = (const float*)d_in[4];
    float* out = (float*)d_out;

    float *yb;
    unsigned *qb, *kvb, *xT, *yT, *wq, *wkv, *wc;
    cudaGetSymbolAddress((void**)&qb,  g_q);
    cudaGetSymbolAddress((void**)&kvb, g_kv);
    cudaGetSymbolAddress((void**)&yb,  g_y);
    cudaGetSymbolAddress((void**)&xT,  g_xT);
    cudaGetSymbolAddress((void**)&yT,  g_yT);
    cudaGetSymbolAddress((void**)&wq,  g_wq);
    cudaGetSymbolAddress((void**)&wkv, g_wkv);
    cudaGetSymbolAddress((void**)&wc,  g_wc);

    const int M = BATCH * SEQ;   // 8192
    dim3 blk(256);

    // --- pre-passes: convert weights, transpose+convert x ---
    cvt_kernel<<<(CDIM * CDIM / 4 + 255) / 256, blk>>>(Wq,  wq,  CDIM * CDIM / 4);
    cvt_kernel<<<(CDIM * KVC  / 4 + 255) / 256, blk>>>(Wkv, wkv, CDIM * KVC / 4);
    cvt_kernel<<<(CDIM * CDIM / 4 + 255) / 256, blk>>>(Wc,  wc,  CDIM * CDIM / 4);
    transpose_cvt_kernel<<<dim3(CDIM / 32, M / 32), dim3(32, 8)>>>(x, xT, M, CDIM);

    // --- projections (tf32-bit outputs feeding flash) ---
    size_t gsm = (size_t)8 * GSTG * 4;   // 64 KB
    cudaFuncSetAttribute(gemm_at_kernel<true>,  cudaFuncAttributeMaxDynamicSharedMemorySize, (int)gsm);
    cudaFuncSetAttribute(gemm_at_kernel<false>, cudaFuncAttributeMaxDynamicSharedMemorySize, (int)gsm);
    gemm_at_kernel<true><<<dim3(CDIM / 128, M / 128), blk, gsm>>>(xT, wq,  nullptr, qb,  M, CDIM, CDIM);
    gemm_at_kernel<true><<<dim3(KVC  / 128, M / 128), blk, gsm>>>(xT, wkv, nullptr, kvb, M, KVC, CDIM);

    // --- flash attention ---
    size_t smem = (size_t)(8448 + 2 * KS_BUF + 2 * VS_BUF + 64 * PS_STR + 192) * 4;
    cudaFuncSetAttribute(flash_kernel, cudaFuncAttributeMaxDynamicSharedMemorySize, (int)smem);
    flash_kernel<<<dim3(SEQ / 64, NH, BATCH), blk, smem>>>();

    // --- output projection (fp32 + bias) ---
    transpose_cvt_kernel<<<dim3(CDIM / 32, M / 32), dim3(32, 8)>>>(yb, yT, M, CDIM);
    gemm_at_kernel<false><<<dim3(CDIM / 128, M / 128), blk, gsm>>>(yT, wc, bc, out, M, CDIM, CDIM);
}

// round 14
// speedup vs baseline: 5.7638x; 1.0548x over previous
#include <cuda_runtime.h>
#include <cuda_bf16.h>
#include <math.h>

#define BATCH 4
#define SEQ   2048
#define CDIM  2048
#define NH    16
#define NKV   4
#define HD    128
#define KVC   1024   // 2*NKV*HD

// Scratch (device globals: allocation-free per harness rules)
__device__ unsigned g_q  [BATCH * SEQ * CDIM];   // q projection, tf32 bits
__device__ unsigned g_kv [BATCH * SEQ * KVC];    // kv projection, tf32 bits
__device__ float    g_y  [BATCH * SEQ * CDIM];   // attention out [B*T, C]
__device__ unsigned g_xT [CDIM * BATCH * SEQ];   // x^T, tf32 bits  [C][B*T]
__device__ unsigned g_yT [CDIM * BATCH * SEQ];   // y^T, tf32 bits  [C][B*T]
__device__ unsigned g_wq [CDIM * CDIM];          // Wq tf32 bits
__device__ unsigned g_wkv[CDIM * KVC];           // Wkv tf32 bits
__device__ unsigned g_wc [CDIM * CDIM];          // Wc tf32 bits

__device__ __forceinline__ unsigned f2tf32(float f) {
    unsigned u;
    asm("cvt.rna.tf32.f32 %0, %1;" : "=r"(u) : "f"(f));
    return u;
}

__device__ __forceinline__ void mma_tf32(float c[4],
    unsigned a0, unsigned a1, unsigned a2, unsigned a3,
    unsigned b0, unsigned b1)
{
    asm volatile(
        "mma.sync.aligned.m16n8k8.row.col.f32.tf32.tf32.f32 "
        "{%0,%1,%2,%3}, {%4,%5,%6,%7}, {%8,%9}, {%0,%1,%2,%3};"
        : "+f"(c[0]), "+f"(c[1]), "+f"(c[2]), "+f"(c[3])
        : "r"(a0), "r"(a1), "r"(a2), "r"(a3), "r"(b0), "r"(b1));
}

__device__ __forceinline__ void cp16(unsigned smem_u32, const void* gptr) {
    asm volatile("cp.async.cg.shared.global [%0], [%1], 16;" :: "r"(smem_u32), "l"(gptr));
}
__device__ __forceinline__ void cp_commit() {
    asm volatile("cp.async.commit_group;");
}
template<int N>
__device__ __forceinline__ void cp_wait() {
    asm volatile("cp.async.wait_group %0;" :: "n"(N));
}

// ---------------------------------------------------------------------------
// Pre-passes
// ---------------------------------------------------------------------------
__global__ __launch_bounds__(256) void cvt_kernel(const float* __restrict__ in,
                                                  unsigned* __restrict__ out, int n4)
{
    int i = (blockIdx.x * 256 + threadIdx.x);
    if (i < n4) {
        float4 v = *(const float4*)(in + (size_t)i * 4);
        uint4 u = {f2tf32(v.x), f2tf32(v.y), f2tf32(v.z), f2tf32(v.w)};
        *(uint4*)(out + (size_t)i * 4) = u;
    }
}

// in: [M][N] fp32 -> out: [N][M] tf32 bits
__global__ __launch_bounds__(256) void transpose_cvt_kernel(
    const float* __restrict__ in, unsigned* __restrict__ out, int M, int N)
{
    __shared__ unsigned tile[32][33];
    int x  = blockIdx.x * 32 + threadIdx.x;
    int y0 = blockIdx.y * 32;
#pragma unroll
    for (int j = 0; j < 32; j += 8)
        tile[threadIdx.y + j][threadIdx.x] =
            f2tf32(in[(size_t)(y0 + threadIdx.y + j) * N + x]);
    __syncthreads();
    int xo = y0 + threadIdx.x;
    int yo = blockIdx.x * 32;
#pragma unroll
    for (int j = 0; j < 32; j += 8)
        out[(size_t)(yo + threadIdx.y + j) * M + xo] = tile[threadIdx.x][threadIdx.y + j];
}

// ---------------------------------------------------------------------------
// TF32 GEMM: C[M,N] = A^T(tf32)[K,M] ^T @ B(tf32)[K,N] (+bias)  (unchanged)
// ---------------------------------------------------------------------------
#define GSTG 2048              // words per stage per operand (16*128)

template<bool TF32OUT>
__global__ __launch_bounds__(256, 2) void gemm_at_kernel(
    const unsigned* __restrict__ AT, const unsigned* __restrict__ B,
    const float* __restrict__ bias, void* __restrict__ Cv,
    int M, int N, int K)
{
    extern __shared__ unsigned sh[];
    unsigned* AsBase = sh;
    unsigned* BsBase = sh + 4 * GSTG;

    const int tid  = threadIdx.x;
    const int lane = tid & 31;
    const int warp = tid >> 5;
    const int tg   = lane & 3;
    const int gid  = lane >> 2;
    const int warpM = (warp & 1) * 64;
    const int warpN = (warp >> 1) * 32;

    const int blockRow = blockIdx.y * 128;
    const int blockCol = blockIdx.x * 128;

    const int k_a  = tid >> 5;
    const int g_a  = tid & 31;
    const unsigned smem_as = (unsigned)__cvta_generic_to_shared(AsBase);
    const unsigned smem_bs = (unsigned)__cvta_generic_to_shared(BsBase);

    int colA[4][2], colB[4];
#pragma unroll
    for (int mt = 0; mt < 4; mt++) {
        int mb = warpM + mt * 16 + gid;
        colA[mt][0] = (((mb) >> 2) ^ (2 * tg)) * 4 + (mb & 3);
        int mb8 = mb + 8;
        colA[mt][1] = (((mb8) >> 2) ^ (2 * tg)) * 4 + (mb8 & 3);
    }
#pragma unroll
    for (int nt = 0; nt < 4; nt++) {
        int nb = warpN + nt * 8 + gid;
        colB[nt] = (((nb) >> 2) ^ (2 * tg)) * 4 + (nb & 3);
    }

    float c[4][4][4];
#pragma unroll
    for (int mt = 0; mt < 4; mt++)
#pragma unroll
        for (int nt = 0; nt < 4; nt++)
#pragma unroll
            for (int i = 0; i < 4; i++) c[mt][nt][i] = 0.f;

    const int nT = K / 16;

    auto issue = [&](int stage_slot, int k0) {
#pragma unroll
        for (int h = 0; h < 2; h++) {
            int k = k_a + h * 8;
            int g = g_a;
            int gsw = g ^ (2 * (k & 3));
            unsigned dA = smem_as + (stage_slot * GSTG + k * 128 + gsw * 4) * 4u;
            unsigned dB = smem_bs + (stage_slot * GSTG + k * 128 + gsw * 4) * 4u;
            cp16(dA, AT + (size_t)(k0 + k) * M + blockRow + g * 4);
            cp16(dB, B  + (size_t)(k0 + k) * N + blockCol + g * 4);
        }
        cp_commit();
    };

    issue(0, 0);
    issue(1, 16);
    issue(2, 32);

    for (int t = 0; t < nT; ++t) {
        cp_wait<2>();
        __syncthreads();

        int nxt = t + 3;
        if (nxt < nT) issue(nxt & 3, nxt * 16);

        const int st = t & 3;
        const unsigned* As = AsBase + st * GSTG;
        const unsigned* Bs = BsBase + st * GSTG;

#pragma unroll
        for (int kk = 0; kk < 16; kk += 8) {
            const unsigned* a0r = As + (kk + tg) * 128;
            const unsigned* a1r = a0r + 4 * 128;
            const unsigned* b0r = Bs + (kk + tg) * 128;
            const unsigned* b1r = b0r + 4 * 128;

            unsigned af[4][4];
#pragma unroll
            for (int mt = 0; mt < 4; mt++) {
                af[mt][0] = a0r[colA[mt][0]];
                af[mt][1] = a0r[colA[mt][1]];
                af[mt][2] = a1r[colA[mt][0]];
                af[mt][3] = a1r[colA[mt][1]];
            }
            unsigned bf[4][2];
#pragma unroll
            for (int nt = 0; nt < 4; nt++) {
                bf[nt][0] = b0r[colB[nt]];
                bf[nt][1] = b1r[colB[nt]];
            }
#pragma unroll
            for (int mt = 0; mt < 4; mt++)
#pragma unroll
                for (int nt = 0; nt < 4; nt++)
                    mma_tf32(c[mt][nt], af[mt][0], af[mt][1], af[mt][2], af[mt][3],
                             bf[nt][0], bf[nt][1]);
        }
        __syncthreads();
    }

#pragma unroll
    for (int mt = 0; mt < 4; mt++) {
        int row = blockRow + warpM + mt * 16 + gid;
#pragma unroll
        for (int nt = 0; nt < 4; nt++) {
            int col = blockCol + warpN + nt * 8 + 2 * tg;
            float b0 = bias ? bias[col] : 0.f;
            float b1 = bias ? bias[col + 1] : 0.f;
            float v00 = c[mt][nt][0] + b0, v01 = c[mt][nt][1] + b1;
            float v10 = c[mt][nt][2] + b0, v11 = c[mt][nt][3] + b1;
            if (TF32OUT) {
                unsigned* C = (unsigned*)Cv;
                uint2 u0 = {f2tf32(v00), f2tf32(v01)};
                uint2 u1 = {f2tf32(v10), f2tf32(v11)};
                *(uint2*)&C[(size_t)row * N + col]       = u0;
                *(uint2*)&C[(size_t)(row + 8) * N + col] = u1;
            } else {
                float* C = (float*)Cv;
                float2 f0 = {v00, v01};
                float2 f1 = {v10, v11};
                *(float2*)&C[(size_t)row * N + col]       = f0;
                *(float2*)&C[(size_t)(row + 8) * N + col] = f1;
            }
        }
    }
}

// ---------------------------------------------------------------------------
// Flash attention v4: 128-row q tiles, tf32 mma, fp32 online softmax.
// grid (T/128, H, B), 256 threads (8 warps, 16 q-rows each).
// K single-buffered (refill overlaps softmax+PV), V double-buffered.
// Smem (words): Q[128][132] | K[64][132] | V[2][64][136] | P[128][68] | m/l/a
// ---------------------------------------------------------------------------
#define QSTR 132
#define KSTR 132
#define VSTR 136
#define PSTR 68
#define OFF_K   (128 * QSTR)            // 16896
#define OFF_V0  (OFF_K + 64 * KSTR)     // 25344
#define OFF_V1  (OFF_V0 + 64 * VSTR)    // 34048
#define OFF_P   (OFF_V1 + 64 * VSTR)    // 42752
#define OFF_M   (OFF_P + 128 * PSTR)    // 51456
#define FL_WORDS (OFF_M + 3 * 128)      // 51840 words = 202.5 KB

__global__ __launch_bounds__(256, 1) void flash_kernel()
{
    extern __shared__ unsigned smu[];
    unsigned* Qs = smu;
    unsigned* Ks = smu + OFF_K;
    unsigned* Ps = smu + OFF_P;
    float* Sf   = (float*)Ps;
    float* Mrow = (float*)(smu + OFF_M);
    float* Lrow = Mrow + 128;
    float* Arow = Lrow + 128;

    const int tid  = threadIdx.x;
    const int lane = tid & 31;
    const int warp = tid >> 5;
    const int tg   = lane & 3;
    const int gid  = lane >> 2;
    const int wm   = warp * 16;          // q-row offset of this warp

    const int b    = blockIdx.z;
    const int h    = blockIdx.y;
    const int hkv  = h >> 2;
    const int row0 = blockIdx.x * 128;
    const float scale = 0.08838834764831845f;

    const unsigned smem_base = (unsigned)__cvta_generic_to_shared(smu);

    // cp.async of one 64-row K/V tile (2048 granules / 256 thr = 8 each)
    auto issueV = [&](int jt) {
        const unsigned vbase = smem_base + ((jt & 1) ? OFF_V1 : OFF_V0) * 4u;
        const int col0 = jt * 64;
#pragma unroll
        for (int i = 0; i < 8; i++) {
            int g = tid + i * 256;
            int r = g >> 5, d4 = g & 31;
            const unsigned* src = g_kv + ((size_t)(b * SEQ + col0 + r)) * KVC + hkv * HD + 512 + d4 * 4;
            cp16(vbase + (r * VSTR + d4 * 4) * 4u, src);
        }
        cp_commit();
    };
    auto issueK = [&](int jt) {
        const unsigned kbase = smem_base + OFF_K * 4u;
        const int col0 = jt * 64;
#pragma unroll
        for (int i = 0; i < 8; i++) {
            int g = tid + i * 256;
            int r = g >> 5, d4 = g & 31;
            const unsigned* src = g_kv + ((size_t)(b * SEQ + col0 + r)) * KVC + hkv * HD + d4 * 4;
            cp16(kbase + (r * KSTR + d4 * 4) * 4u, src);
        }
        cp_commit();
    };

    // Load Q tile [128][128] (tf32 bits)
    for (int idx = tid; idx < 128 * 32; idx += 256) {
        int r = idx >> 5, d4 = idx & 31;
        uint4 u = *(const uint4*)&g_q[((size_t)(b * SEQ + row0 + r)) * CDIM + h * HD + d4 * 4];
        *(uint4*)&Qs[r * QSTR + d4 * 4] = u;
    }
    if (tid < 128) { Mrow[tid] = -1e30f; Lrow[tid] = 0.f; }

    float oacc[16][4];
#pragma unroll
    for (int nt = 0; nt < 16; nt++)
#pragma unroll
        for (int i = 0; i < 4; i++) oacc[nt][i] = 0.f;

    const int ntiles = 2 * blockIdx.x + 2;   // keys 0 .. row0+127
    issueV(0);
    issueK(0);

    for (int jt = 0; jt < ntiles; ++jt) {
        const int col0 = jt * 64;
        const bool mask = (jt >= ntiles - 2);
        const unsigned* Vs = smu + ((jt & 1) ? OFF_V1 : OFF_V0);

        cp_wait<0>();          // K(jt), V(jt) resident
        __syncthreads();       // all warps past prior reads of K buf / V(jt-1) buf

        if (jt + 1 < ntiles) issueV(jt + 1);   // into buffer freed by PV(jt-1)

        // ---- S = Q @ K^T : 128x64, each warp 16 rows x 64 cols ----
        float sacc[8][4];
#pragma unroll
        for (int nt = 0; nt < 8; nt++)
#pragma unroll
            for (int i = 0; i < 4; i++) sacc[nt][i] = 0.f;

#pragma unroll
        for (int d0 = 0; d0 < HD; d0 += 8) {
            unsigned a0 = Qs[(wm + gid) * QSTR + d0 + tg];
            unsigned a1 = Qs[(wm + gid + 8) * QSTR + d0 + tg];
            unsigned a2 = Qs[(wm + gid) * QSTR + d0 + tg + 4];
            unsigned a3 = Qs[(wm + gid + 8) * QSTR + d0 + tg + 4];
#pragma unroll
            for (int nt = 0; nt < 8; nt++) {
                int kr = nt * 8 + gid;
                unsigned b0 = Ks[kr * KSTR + d0 + tg];
                unsigned b1 = Ks[kr * KSTR + d0 + tg + 4];
                mma_tf32(sacc[nt], a0, a1, a2, a3, b0, b1);
            }
        }

        // scale + mask + store S (fp32)
#pragma unroll
        for (int nt = 0; nt < 8; nt++) {
            int colL = nt * 8 + 2 * tg;
            int col_g = col0 + colL;
            int rq0 = row0 + wm + gid;
            int rq1 = rq0 + 8;
            float s0 = sacc[nt][0] * scale;
            float s1 = sacc[nt][1] * scale;
            float s2 = sacc[nt][2] * scale;
            float s3 = sacc[nt][3] * scale;
            if (mask) {
                if (col_g > rq0)     s0 = -1e30f;
                if (col_g + 1 > rq0) s1 = -1e30f;
                if (col_g > rq1)     s2 = -1e30f;
                if (col_g + 1 > rq1) s3 = -1e30f;
            }
            float2 p0 = {s0, s1}, p1 = {s2, s3};
            *(float2*)&Sf[(wm + gid) * PSTR + colL]     = p0;
            *(float2*)&Sf[(wm + gid + 8) * PSTR + colL] = p1;
        }
        __syncthreads();        // all S reads of Ks done -> safe to refill K

        if (jt + 1 < ntiles) issueK(jt + 1);   // overlaps softmax + PV

        // ---- online softmax: 2 lanes/row, interleaved columns ----
        {
            const int rr = tid >> 1;
            const int hh = tid & 1;
            float mloc = -1e30f;
#pragma unroll
            for (int c = 0; c < 32; c++) mloc = fmaxf(mloc, Sf[rr * PSTR + hh + 2 * c]);
            mloc = fmaxf(mloc, __shfl_xor_sync(0xffffffffu, mloc, 1));
            float mold = Mrow[rr];
            float mnew = fmaxf(mold, mloc);
            float lloc = 0.f;
#pragma unroll
            for (int c = 0; c < 32; c++) {
                float p = __expf(Sf[rr * PSTR + hh + 2 * c] - mnew);
                Ps[rr * PSTR + hh + 2 * c] = f2tf32(p);
                lloc += p;
            }
            lloc += __shfl_xor_sync(0xffffffffu, lloc, 1);
            if (hh == 0) {
                float alpha = __expf(mold - mnew);
                Mrow[rr] = mnew;
                Lrow[rr] = Lrow[rr] * alpha + lloc;
                Arow[rr] = alpha;
            }
        }
        __syncthreads();

        // ---- O = alpha*O + P @ V : each warp 16 rows x 128 d ----
        {
            float al0 = Arow[wm + gid];
            float al1 = Arow[wm + gid + 8];
#pragma unroll
            for (int nt = 0; nt < 16; nt++) {
                oacc[nt][0] *= al0; oacc[nt][1] *= al0;
                oacc[nt][2] *= al1; oacc[nt][3] *= al1;
            }
#pragma unroll
            for (int k0 = 0; k0 < 64; k0 += 8) {
                unsigned a0 = Ps[(wm + gid) * PSTR + k0 + tg];
                unsigned a1 = Ps[(wm + gid + 8) * PSTR + k0 + tg];
                unsigned a2 = Ps[(wm + gid) * PSTR + k0 + tg + 4];
                unsigned a3 = Ps[(wm + gid + 8) * PSTR + k0 + tg + 4];
#pragma unroll
                for (int nt = 0; nt < 16; nt++) {
                    int nb = nt * 8 + gid;
                    unsigned b0 = Vs[(k0 + tg) * VSTR + nb];
                    unsigned b1 = Vs[(k0 + tg + 4) * VSTR + nb];
                    mma_tf32(oacc[nt], a0, a1, a2, a3, b0, b1);
                }
            }
        }
        // no trailing sync: next iter's wait+sync covers buffer reuse
    }

    // normalize + write out
    {
        float linv0 = 1.f / Lrow[wm + gid];
        float linv1 = 1.f / Lrow[wm + gid + 8];
        size_t r0g = ((size_t)(b * SEQ + row0 + wm + gid)) * CDIM + h * HD;
        size_t r1g = r0g + (size_t)8 * CDIM;
#pragma unroll
        for (int nt = 0; nt < 16; nt++) {
            int col = nt * 8 + 2 * tg;
            float2 v0 = {oacc[nt][0] * linv0, oacc[nt][1] * linv0};
            float2 v1 = {oacc[nt][2] * linv1, oacc[nt][3] * linv1};
            *(float2*)&g_y[r0g + col] = v0;
            *(float2*)&g_y[r1g + col] = v1;
        }
    }
}

// ---------------------------------------------------------------------------
extern "C" void kernel_launch(void* const* d_in, const int* in_sizes, int n_in,
                              void* d_out, int out_size)
{
    const float* x   = (const float*)d_in[0];
    const float* Wq  = (const float*)d_in[1];
    const float* Wkv = (const float*)d_in[2];
    const float* Wc  = (const float*)d_in[3];
    const float* bc  = (const float*)d_in[4];
    float* out = (float*)d_out;

    float *yb;
    unsigned *qb, *kvb, *xT, *yT, *wq, *wkv, *wc;
    cudaGetSymbolAddress((void**)&qb,  g_q);
    cudaGetSymbolAddress((void**)&kvb, g_kv);
    cudaGetSymbolAddress((void**)&yb,  g_y);
    cudaGetSymbolAddress((void**)&xT,  g_xT);
    cudaGetSymbolAddress((void**)&yT,  g_yT);
    cudaGetSymbolAddress((void**)&wq,  g_wq);
    cudaGetSymbolAddress((void**)&wkv, g_wkv);
    cudaGetSymbolAddress((void**)&wc,  g_wc);

    const int M = BATCH * SEQ;   // 8192
    dim3 blk(256);

    // --- pre-passes: convert weights, transpose+convert x ---
    cvt_kernel<<<(CDIM * CDIM / 4 + 255) / 256, blk>>>(Wq,  wq,  CDIM * CDIM / 4);
    cvt_kernel<<<(CDIM * KVC  / 4 + 255) / 256, blk>>>(Wkv, wkv, CDIM * KVC / 4);
    cvt_kernel<<<(CDIM * CDIM / 4 + 255) / 256, blk>>>(Wc,  wc,  CDIM * CDIM / 4);
    transpose_cvt_kernel<<<dim3(CDIM / 32, M / 32), dim3(32, 8)>>>(x, xT, M, CDIM);

    // --- projections (tf32-bit outputs feeding flash) ---
    size_t gsm = (size_t)8 * GSTG * 4;   // 64 KB
    cudaFuncSetAttribute(gemm_at_kernel<true>,  cudaFuncAttributeMaxDynamicSharedMemorySize, (int)gsm);
    cudaFuncSetAttribute(gemm_at_kernel<false>, cudaFuncAttributeMaxDynamicSharedMemorySize, (int)gsm);
    gemm_at_kernel<true><<<dim3(CDIM / 128, M / 128), blk, gsm>>>(xT, wq,  nullptr, qb,  M, CDIM, CDIM);
    gemm_at_kernel<true><<<dim3(KVC  / 128, M / 128), blk, gsm>>>(xT, wkv, nullptr, kvb, M, KVC, CDIM);

    // --- flash attention (128-row q tiles) ---
    size_t smem = (size_t)FL_WORDS * 4;
    cudaFuncSetAttribute(flash_kernel, cudaFuncAttributeMaxDynamicSharedMemorySize, (int)smem);
    flash_kernel<<<dim3(SEQ / 128, NH, BATCH), blk, smem>>>();

    // --- output projection (fp32 + bias) ---
    transpose_cvt_kernel<<<dim3(CDIM / 32, M / 32), dim3(32, 8)>>>(yb, yT, M, CDIM);
    gemm_at_kernel<false><<<dim3(CDIM / 128, M / 128), blk, gsm>>>(yT, wc, bc, out, M, CDIM, CDIM);
}